// round 8
// baseline (speedup 1.0000x reference)
#include <cuda_runtime.h>
#include <cuda_bf16.h>
#include <cstdint>

#define BATCH  8
#define SEQ    1024
#define NH     12
#define HD     64
#define HIDDEN 768
#define KSEL   6

// ---------------- device scratch (no allocations allowed) ----------------
__device__ float g_mask[BATCH][NH];
__device__ float g_rsum[BATCH][8][HIDDEN];
__device__ float g_logits[BATCH][NH];
__device__ __align__(16) __nv_bfloat16 g_q16[(size_t)BATCH * NH * SEQ * HD];
__device__ __align__(16) __nv_bfloat16 g_k16[(size_t)BATCH * NH * SEQ * HD];
__device__ __align__(16) __nv_bfloat16 g_v16[(size_t)BATCH * NH * SEQ * HD];
__device__ __align__(16) __nv_bfloat16 g_hs16[(size_t)BATCH * SEQ * HIDDEN];
__device__ __align__(16) __nv_bfloat16 g_ctx16[(size_t)BATCH * SEQ * HIDDEN];
__device__ __align__(16) __nv_bfloat16 g_wt[4][(size_t)HIDDEN * HIDDEN]; // transposed: wt[c][k]=W[k][c]

// ---------------- helpers ----------------
__device__ __forceinline__ uint32_t smem_u32(const void* p) {
    uint32_t a;
    asm("{ .reg .u64 t; cvta.to.shared.u64 t, %1; cvt.u32.u64 %0, t; }" : "=r"(a) : "l"(p));
    return a;
}
#define SWZ(x) ((x) ^ (((x) >> 3) & 0x70))

__device__ __forceinline__ void cp16(uint32_t saddr, const void* g) {
    asm volatile("cp.async.cg.shared.global [%0], [%1], 16;" :: "r"(saddr), "l"(g));
}
#define CP_COMMIT() asm volatile("cp.async.commit_group;")
#define CP_WAIT0()  asm volatile("cp.async.wait_group 0;")

__device__ __forceinline__ void ldm_x4(uint32_t* r, uint32_t addr) {
    asm volatile("ldmatrix.sync.aligned.m8n8.x4.shared.b16 {%0,%1,%2,%3}, [%4];"
                 : "=r"(r[0]), "=r"(r[1]), "=r"(r[2]), "=r"(r[3]) : "r"(addr));
}
__device__ __forceinline__ void ldm_x4t(uint32_t* r, uint32_t addr) {
    asm volatile("ldmatrix.sync.aligned.m8n8.x4.trans.shared.b16 {%0,%1,%2,%3}, [%4];"
                 : "=r"(r[0]), "=r"(r[1]), "=r"(r[2]), "=r"(r[3]) : "r"(addr));
}
__device__ __forceinline__ void mma16816(float* c, const uint32_t* a, const uint32_t* b) {
    asm volatile(
        "mma.sync.aligned.m16n8k16.row.col.f32.bf16.bf16.f32 "
        "{%0,%1,%2,%3}, {%4,%5,%6,%7}, {%8,%9}, {%0,%1,%2,%3};"
        : "+f"(c[0]), "+f"(c[1]), "+f"(c[2]), "+f"(c[3])
        : "r"(a[0]), "r"(a[1]), "r"(a[2]), "r"(a[3]), "r"(b[0]), "r"(b[1]));
}
__device__ __forceinline__ uint32_t packbf2(float x, float y) {
    __nv_bfloat162 v = __floats2bfloat162_rn(x, y);
    return *(uint32_t*)&v;
}

// ---------------- weight convert (transpose + bf16) ----------------
__global__ void conv_wt_kernel(const float* __restrict__ W0, const float* __restrict__ W1,
                               const float* __restrict__ W2, const float* __restrict__ W3) {
    __shared__ float tile[32][33];
    int which = blockIdx.z;
    const float* W = which == 0 ? W0 : (which == 1 ? W1 : (which == 2 ? W2 : W3));
    int k0 = blockIdx.x * 32, c0 = blockIdx.y * 32;
    int tx = threadIdx.x, ty = threadIdx.y;  // 32 x 8
    #pragma unroll
    for (int j = 0; j < 32; j += 8)
        tile[ty + j][tx] = W[(size_t)(k0 + ty + j) * HIDDEN + c0 + tx];
    __syncthreads();
    __nv_bfloat16* wt = g_wt[which];
    #pragma unroll
    for (int j = 0; j < 32; j += 8)
        wt[(size_t)(c0 + ty + j) * HIDDEN + k0 + tx] = __float2bfloat16(tile[tx][ty + j]);
}

// ---------------- router stage 1 + hs bf16 conversion (fused) ------------
__global__ void router_sum_conv_kernel(const float* __restrict__ hs) {
    int b = blockIdx.x, chunk = blockIdx.y, t = threadIdx.x;
    const float* p = hs + ((size_t)b * SEQ + chunk * 128) * HIDDEN;
    // column partial sums over this 128-row chunk
    for (int d = t; d < HIDDEN; d += 256) {
        float a0 = 0.f, a1 = 0.f, a2 = 0.f, a3 = 0.f;
        #pragma unroll 4
        for (int s = 0; s < 128; s += 4) {
            a0 += p[(size_t)(s + 0) * HIDDEN + d];
            a1 += p[(size_t)(s + 1) * HIDDEN + d];
            a2 += p[(size_t)(s + 2) * HIDDEN + d];
            a3 += p[(size_t)(s + 3) * HIDDEN + d];
        }
        g_rsum[b][chunk][d] = (a0 + a1) + (a2 + a3);
    }
    // bf16 conversion of the same chunk (L2-resident second pass)
    const float4* src = (const float4*)p;
    __nv_bfloat162* dst = (__nv_bfloat162*)(g_hs16 + ((size_t)(b * SEQ + chunk * 128)) * HIDDEN);
    const int N4 = 128 * HIDDEN / 4;  // 24576
    for (int i = t; i < N4; i += 256) {
        float4 v = src[i];
        dst[2 * i + 0] = __floats2bfloat162_rn(v.x, v.y);
        dst[2 * i + 1] = __floats2bfloat162_rn(v.z, v.w);
    }
}

// one warp per (batch, head): 96 warps = 12 blocks x 256 threads, fp32
__global__ void router_logit_kernel(const float* __restrict__ Wr,
                                    const float* __restrict__ br) {
    int gw = (blockIdx.x * blockDim.x + threadIdx.x) >> 5;
    int lane = threadIdx.x & 31;
    int b = gw / NH, h = gw % NH;
    if (b >= BATCH) return;
    float acc0 = 0.f, acc1 = 0.f;
    #pragma unroll
    for (int i = 0; i < HIDDEN / 64; i++) {
        int d0 = i * 64 + lane;
        int d1 = d0 + 32;
        float s0 = 0.f, s1 = 0.f;
        #pragma unroll
        for (int c = 0; c < 8; c++) { s0 += g_rsum[b][c][d0]; s1 += g_rsum[b][c][d1]; }
        acc0 += s0 * Wr[d0 * NH + h];
        acc1 += s1 * Wr[d1 * NH + h];
    }
    float acc = acc0 + acc1;
    #pragma unroll
    for (int o = 16; o > 0; o >>= 1)
        acc += __shfl_xor_sync(0xFFFFFFFF, acc, o);
    if (lane == 0)
        g_logits[b][h] = acc / (float)SEQ + br[h];
}

__global__ void router_topk_kernel() {
    int b = threadIdx.x;
    if (b >= BATCH) return;
    float lg[NH];
    #pragma unroll
    for (int h = 0; h < NH; h++) lg[h] = g_logits[b][h];
    bool sel[NH];
    #pragma unroll
    for (int h = 0; h < NH; h++) sel[h] = false;
    for (int k = 0; k < KSEL; k++) {
        int best = -1; float bv = 0.f;
        for (int h = 0; h < NH; h++)
            if (!sel[h] && (best < 0 || lg[h] > bv)) { bv = lg[h]; best = h; }
        sel[best] = true;
    }
    for (int h = 0; h < NH; h++) g_mask[b][h] = sel[h] ? 1.f : 0.f;
}

// ---------------- QKV: fused q+k+v HMMA GEMM (128s x 3x64n per CTA) -------
// smem: A 2x16KB @0 ; B 2 bufs x 3 secs x 8KB @32768  => 80KB
#define QKV_SMEM 81920

__global__ __launch_bounds__(256) void qkv_hmma_kernel(const float* __restrict__ bq,
                                                       const float* __restrict__ bk,
                                                       const float* __restrict__ bv) {
    int t = threadIdx.x, wid = t >> 5, lane = t & 31;
    int s0 = blockIdx.x * 128;
    int h = blockIdx.y % NH, b = blockIdx.y / NH;
    if (g_mask[b][h] == 0.f) return;

    extern __shared__ char dsm[];
    uint32_t sbA = smem_u32(dsm);           // 2 x 16384
    uint32_t sbB = sbA + 32768;             // 2 x (3 x 8192)

    const __nv_bfloat16* Asrc = g_hs16 + ((size_t)(b * SEQ + s0)) * HIDDEN;
    const __nv_bfloat16* B0 = g_wt[0] + ((size_t)h * 64) * HIDDEN;
    const __nv_bfloat16* B1 = g_wt[1] + ((size_t)h * 64) * HIDDEN;
    const __nv_bfloat16* B2 = g_wt[2] + ((size_t)h * 64) * HIDDEN;

    int m0 = (wid & 3) * 32, n0 = (wid >> 2) * 32;
    float acc[3][2][4][4];
    #pragma unroll
    for (int sc = 0; sc < 3; sc++)
        #pragma unroll
        for (int i = 0; i < 2; i++)
            #pragma unroll
            for (int j = 0; j < 4; j++)
                #pragma unroll
                for (int x = 0; x < 4; x++) acc[sc][i][j][x] = 0.f;

    auto load_chunk = [&](int buf, int k0) {
        uint32_t ab = sbA + buf * 16384;
        #pragma unroll
        for (int i = 0; i < 4; i++) {
            int u = i * 256 + t, row = u >> 3, ch = u & 7;
            cp16(ab + SWZ(row * 128 + ch * 16), Asrc + (size_t)row * HIDDEN + k0 + ch * 8);
        }
        uint32_t bb = sbB + buf * 24576;
        #pragma unroll
        for (int i = 0; i < 2; i++) {
            int u = i * 256 + t, row = u >> 3, ch = u & 7;
            uint32_t so = SWZ(row * 128 + ch * 16);
            size_t go = (size_t)row * HIDDEN + k0 + ch * 8;
            cp16(bb + so,          B0 + go);
            cp16(bb + 8192 + so,   B1 + go);
            cp16(bb + 16384 + so,  B2 + go);
        }
    };

    load_chunk(0, 0);
    CP_COMMIT();
    int cur = 0;
    const int NC = HIDDEN / 64;
    int rowA = m0 + ((lane >> 3) & 1) * 8 + (lane & 7);
    int koA  = (lane >> 4) * 16;
    int rowB = n0 + (lane >> 4) * 8 + (lane & 7);
    int koB  = ((lane >> 3) & 1) * 16;
    for (int c = 0; c < NC; c++) {
        CP_WAIT0();
        __syncthreads();
        if (c + 1 < NC) { load_chunk(cur ^ 1, (c + 1) * 64); CP_COMMIT(); }
        uint32_t aBase = sbA + cur * 16384;
        uint32_t bBase = sbB + cur * 24576;
        #pragma unroll
        for (int kk = 0; kk < 4; kk++) {
            int kb = kk * 32;
            uint32_t a[2][4];
            #pragma unroll
            for (int mt = 0; mt < 2; mt++)
                ldm_x4(a[mt], aBase + SWZ((rowA + mt * 16) * 128 + kb + koA));
            #pragma unroll
            for (int sc = 0; sc < 3; sc++) {
                uint32_t bf[2][4];
                #pragma unroll
                for (int hf = 0; hf < 2; hf++)
                    ldm_x4(bf[hf], bBase + sc * 8192 + SWZ((rowB + hf * 16) * 128 + kb + koB));
                #pragma unroll
                for (int mt = 0; mt < 2; mt++)
                    #pragma unroll
                    for (int nt = 0; nt < 4; nt++)
                        mma16816(acc[sc][mt][nt], a[mt], &bf[nt >> 1][(nt & 1) * 2]);
            }
        }
        cur ^= 1;
    }

    #pragma unroll
    for (int sc = 0; sc < 3; sc++) {
        const float* bias = sc == 0 ? bq : (sc == 1 ? bk : bv);
        __nv_bfloat16* base = sc == 0 ? g_q16 : (sc == 1 ? g_k16 : g_v16);
        __nv_bfloat16* dst = base + (((size_t)b * NH + h) * SEQ + s0) * HD;
        #pragma unroll
        for (int mt = 0; mt < 2; mt++)
            #pragma unroll
            for (int nt = 0; nt < 4; nt++) {
                int r = m0 + mt * 16 + (lane >> 2);
                int cc = n0 + nt * 8 + (lane & 3) * 2;
                float b0 = bias[h * 64 + cc], b1 = bias[h * 64 + cc + 1];
                *(__nv_bfloat162*)(dst + (size_t)r * HD + cc) =
                    __floats2bfloat162_rn(acc[sc][mt][nt][0] + b0, acc[sc][mt][nt][1] + b1);
                *(__nv_bfloat162*)(dst + (size_t)(r + 8) * HD + cc) =
                    __floats2bfloat162_rn(acc[sc][mt][nt][2] + b0, acc[sc][mt][nt][3] + b1);
            }
    }
}

// ---------------- attention: HMMA flash (no max-shift; scores bounded) -----
#define ATT_SMEM 49152

__global__ __launch_bounds__(256, 2) void attn_hmma_kernel() {
    int b = blockIdx.y / NH, h = blockIdx.y % NH;
    if (g_mask[b][h] == 0.f) return;
    int t = threadIdx.x, wid = t >> 5, lane = t & 31;
    int s0 = blockIdx.x * 128;

    extern __shared__ char dsm[];
    uint32_t sQ = smem_u32(dsm);
    uint32_t sK = sQ + 16384;
    uint32_t sV = sQ + 32768;

    const __nv_bfloat16* qsrc = g_q16 + (((size_t)b * NH + h) * SEQ + s0) * HD;
    const __nv_bfloat16* ksrc = g_k16 + (((size_t)b * NH + h) * SEQ) * HD;
    const __nv_bfloat16* vsrc = g_v16 + (((size_t)b * NH + h) * SEQ) * HD;

    #pragma unroll
    for (int i = 0; i < 4; i++) {
        int u = i * 256 + t, row = u >> 3, ch = u & 7;
        cp16(sQ + SWZ(row * 128 + ch * 16), qsrc + (size_t)row * HD + ch * 8);
    }
    auto load_kv = [&](int buf, int kt) {
        #pragma unroll
        for (int i = 0; i < 2; i++) {
            int u = i * 256 + t, row = u >> 3, ch = u & 7;
            cp16(sK + buf * 8192 + SWZ(row * 128 + ch * 16),
                 ksrc + (size_t)(kt * 64 + row) * HD + ch * 8);
            cp16(sV + buf * 8192 + SWZ(row * 128 + ch * 16),
                 vsrc + (size_t)(kt * 64 + row) * HD + ch * 8);
        }
    };
    load_kv(0, 0);
    CP_COMMIT();

    int m0 = wid * 16;
    float o[8][4];
    #pragma unroll
    for (int i = 0; i < 8; i++)
        #pragma unroll
        for (int j = 0; j < 4; j++) o[i][j] = 0.f;
    float l0 = 0.f, l1 = 0.f;

    int rowA = m0 + ((lane >> 3) & 1) * 8 + (lane & 7);
    int koA  = (lane >> 4) * 16;
    int rowBb = (lane >> 4) * 8 + (lane & 7);
    int koB  = ((lane >> 3) & 1) * 16;
    int rowV = ((lane >> 3) & 1) * 8 + (lane & 7);
    int koV  = ((lane >> 4) & 1) * 16;

    int cur = 0;
    for (int kt = 0; kt < SEQ / 64; kt++) {
        CP_WAIT0();
        __syncthreads();
        if (kt + 1 < SEQ / 64) { load_kv(cur ^ 1, kt + 1); CP_COMMIT(); }

        uint32_t kBase = sK + cur * 8192;
        uint32_t vBase = sV + cur * 8192;

        float s[8][4];
        #pragma unroll
        for (int i = 0; i < 8; i++)
            #pragma unroll
            for (int j = 0; j < 4; j++) s[i][j] = 0.f;
        #pragma unroll
        for (int ds = 0; ds < 4; ds++) {
            uint32_t qa[4];
            ldm_x4(qa, sQ + SWZ(rowA * 128 + ds * 32 + koA));
            #pragma unroll
            for (int nf = 0; nf < 4; nf++) {
                uint32_t kb4[4];
                ldm_x4(kb4, kBase + SWZ((nf * 16 + rowBb) * 128 + ds * 32 + koB));
                mma16816(s[2 * nf + 0], qa, &kb4[0]);
                mma16816(s[2 * nf + 1], qa, &kb4[2]);
            }
        }
        uint32_t pa[4][4];
        #pragma unroll
        for (int nf = 0; nf < 8; nf++) {
            s[nf][0] = __expf(s[nf][0] * 0.125f);
            s[nf][1] = __expf(s[nf][1] * 0.125f);
            s[nf][2] = __expf(s[nf][2] * 0.125f);
            s[nf][3] = __expf(s[nf][3] * 0.125f);
            l0 += s[nf][0] + s[nf][1];
            l1 += s[nf][2] + s[nf][3];
        }
        #pragma unroll
        for (int ks = 0; ks < 4; ks++) {
            pa[ks][0] = packbf2(s[2 * ks][0],     s[2 * ks][1]);
            pa[ks][1] = packbf2(s[2 * ks][2],     s[2 * ks][3]);
            pa[ks][2] = packbf2(s[2 * ks + 1][0], s[2 * ks + 1][1]);
            pa[ks][3] = packbf2(s[2 * ks + 1][2], s[2 * ks + 1][3]);
        }
        #pragma unroll
        for (int ks = 0; ks < 4; ks++) {
            #pragma unroll
            for (int dh = 0; dh < 4; dh++) {
                uint32_t vb[4];
                ldm_x4t(vb, vBase + SWZ((ks * 16 + rowV) * 128 + dh * 32 + koV));
                mma16816(o[2 * dh + 0], pa[ks], &vb[0]);
                mma16816(o[2 * dh + 1], pa[ks], &vb[2]);
            }
        }
        cur ^= 1;
    }

    l0 += __shfl_xor_sync(0xFFFFFFFF, l0, 1);
    l0 += __shfl_xor_sync(0xFFFFFFFF, l0, 2);
    l1 += __shfl_xor_sync(0xFFFFFFFF, l1, 1);
    l1 += __shfl_xor_sync(0xFFFFFFFF, l1, 2);
    float inv0 = 1.f / l0, inv1 = 1.f / l1;

    int r0 = s0 + m0 + (lane >> 2);
    __nv_bfloat16* c0 = g_ctx16 + ((size_t)(b * SEQ + r0)) * HIDDEN + h * 64;
    __nv_bfloat16* c1 = c0 + (size_t)8 * HIDDEN;
    #pragma unroll
    for (int dn = 0; dn < 8; dn++) {
        int d = dn * 8 + (lane & 3) * 2;
        *(__nv_bfloat162*)(c0 + d) = __floats2bfloat162_rn(o[dn][0] * inv0, o[dn][1] * inv0);
        *(__nv_bfloat162*)(c1 + d) = __floats2bfloat162_rn(o[dn][2] * inv1, o[dn][3] * inv1);
    }
}

// ---------------- Wo: HMMA bf16, active-head K only, bias+residual fused ---
#define WO_SMEM 65536

__global__ __launch_bounds__(256) void wo_hmma_kernel(const float* __restrict__ hs,
                                                      const float* __restrict__ bo,
                                                      float* __restrict__ out) {
    int t = threadIdx.x, wid = t >> 5, lane = t & 31;
    int s0 = blockIdx.x * 128;
    int col0 = blockIdx.y * 128;
    int b = blockIdx.z;

    int act[KSEL]; int na = 0;
    #pragma unroll
    for (int h = 0; h < NH; h++)
        if (g_mask[b][h] != 0.f) { if (na < KSEL) act[na] = h; na++; }

    extern __shared__ char dsm[];
    uint32_t sbA = smem_u32(dsm);
    uint32_t sbB = sbA + 32768;

    int m0 = (wid & 3) * 32, n0 = (wid >> 2) * 64;
    float acc[2][8][4];
    #pragma unroll
    for (int i = 0; i < 2; i++)
        #pragma unroll
        for (int j = 0; j < 8; j++)
            #pragma unroll
            for (int x = 0; x < 4; x++) acc[i][j][x] = 0.f;

    auto load_chunk = [&](int buf, int h) {
        const __nv_bfloat16* Asrc = g_ctx16 + ((size_t)(b * SEQ + s0)) * HIDDEN + h * 64;
        uint32_t ab = sbA + buf * 16384;
        #pragma unroll
        for (int i = 0; i < 4; i++) {
            int u = i * 256 + t, row = u >> 3, ch = u & 7;
            cp16(ab + SWZ(row * 128 + ch * 16), Asrc + (size_t)row * HIDDEN + ch * 8);
        }
        const __nv_bfloat16* Bsrc = g_wt[3] + ((size_t)col0) * HIDDEN + h * 64;
        uint32_t bb = sbB + buf * 16384;
        #pragma unroll
        for (int i = 0; i < 4; i++) {
            int u = i * 256 + t, row = u >> 3, ch = u & 7;
            cp16(bb + SWZ(row * 128 + ch * 16), Bsrc + (size_t)row * HIDDEN + ch * 8);
        }
    };

    load_chunk(0, act[0]);
    CP_COMMIT();
    int cur = 0;
    for (int c = 0; c < KSEL; c++) {
        CP_WAIT0();
        __syncthreads();
        if (c + 1 < KSEL) { load_chunk(cur ^ 1, act[c + 1]); CP_COMMIT(); }
        uint32_t aBase = sbA + cur * 16384;
        uint32_t bBase = sbB + cur * 16384;
        #pragma unroll
        for (int kk = 0; kk < 4; kk++) {
            int kb = kk * 32;
            uint32_t a[2][4], bf[4][4];
            #pragma unroll
            for (int mt = 0; mt < 2; mt++) {
                int row = m0 + mt * 16 + ((lane >> 3) & 1) * 8 + (lane & 7);
                int ko = kb + (lane >> 4) * 16;
                ldm_x4(a[mt], aBase + SWZ(row * 128 + ko));
            }
            #pragma unroll
            for (int hf = 0; hf < 4; hf++) {
                int row = n0 + hf * 16 + (lane >> 4) * 8 + (lane & 7);
                int ko = kb + ((lane >> 3) & 1) * 16;
                ldm_x4(bf[hf], bBase + SWZ(row * 128 + ko));
            }
            #pragma unroll
            for (int mt = 0; mt < 2; mt++)
                #pragma unroll
                for (int nt = 0; nt < 8; nt++)
                    mma16816(acc[mt][nt], a[mt], &bf[nt >> 1][(nt & 1) * 2]);
        }
        cur ^= 1;
    }

    #pragma unroll
    for (int mt = 0; mt < 2; mt++)
        #pragma unroll
        for (int nt = 0; nt < 8; nt++) {
            int r = s0 + m0 + mt * 16 + (lane >> 2);
            int cc = col0 + n0 + nt * 8 + (lane & 3) * 2;
            float b0 = bo[cc], b1 = bo[cc + 1];
            float2 r0 = *(const float2*)(hs + ((size_t)(b * SEQ + r)) * HIDDEN + cc);
            float2 r1 = *(const float2*)(hs + ((size_t)(b * SEQ + r + 8)) * HIDDEN + cc);
            float2 v0 = make_float2(acc[mt][nt][0] + b0 + r0.x, acc[mt][nt][1] + b1 + r0.y);
            float2 v1 = make_float2(acc[mt][nt][2] + b0 + r1.x, acc[mt][nt][3] + b1 + r1.y);
            *(float2*)(out + ((size_t)(b * SEQ + r)) * HIDDEN + cc) = v0;
            *(float2*)(out + ((size_t)(b * SEQ + r + 8)) * HIDDEN + cc) = v1;
        }
}

// ---------------- LayerNorm in-place ----------------
__global__ void ln_kernel(float* __restrict__ x, const float* __restrict__ g,
                          const float* __restrict__ bb) {
    int row = blockIdx.x;
    int t = threadIdx.x;
    float* p = x + (size_t)row * HIDDEN;
    float v0 = p[t], v1 = p[t + 256], v2 = p[t + 512];
    __shared__ float red[256];
    red[t] = v0 + v1 + v2;
    __syncthreads();
    for (int o = 128; o > 0; o >>= 1) { if (t < o) red[t] += red[t + o]; __syncthreads(); }
    float mu = red[0] * (1.f / HIDDEN);
    __syncthreads();
    float d0 = v0 - mu, d1 = v1 - mu, d2 = v2 - mu;
    red[t] = d0 * d0 + d1 * d1 + d2 * d2;
    __syncthreads();
    for (int o = 128; o > 0; o >>= 1) { if (t < o) red[t] += red[t + o]; __syncthreads(); }
    float rs = rsqrtf(red[0] * (1.f / HIDDEN) + 1e-12f);
    p[t]       = d0 * rs * g[t]       + bb[t];
    p[t + 256] = d1 * rs * g[t + 256] + bb[t + 256];
    p[t + 512] = d2 * rs * g[t + 512] + bb[t + 512];
}

// ---------------------------------------------------------------------------
extern "C" void kernel_launch(void* const* d_in, const int* in_sizes, int n_in,
                              void* d_out, int out_size) {
    (void)in_sizes; (void)n_in; (void)out_size;
    const float* hs = (const float*)d_in[0];
    const float* Wq = (const float*)d_in[1];
    const float* bq = (const float*)d_in[2];
    const float* Wk = (const float*)d_in[3];
    const float* bk = (const float*)d_in[4];
    const float* Wv = (const float*)d_in[5];
    const float* bv = (const float*)d_in[6];
    const float* Wr = (const float*)d_in[7];
    const float* br = (const float*)d_in[8];
    const float* Wo = (const float*)d_in[9];
    const float* bo = (const float*)d_in[10];
    const float* lg = (const float*)d_in[11];
    const float* lb = (const float*)d_in[12];
    float* out = (float*)d_out;

    cudaFuncSetAttribute(qkv_hmma_kernel, cudaFuncAttributeMaxDynamicSharedMemorySize, QKV_SMEM);
    cudaFuncSetAttribute(attn_hmma_kernel, cudaFuncAttributeMaxDynamicSharedMemorySize, ATT_SMEM);
    cudaFuncSetAttribute(wo_hmma_kernel,  cudaFuncAttributeMaxDynamicSharedMemorySize, WO_SMEM);

    conv_wt_kernel<<<dim3(24, 24, 4), dim3(32, 8)>>>(Wq, Wk, Wv, Wo);
    router_sum_conv_kernel<<<dim3(BATCH, 8), 256>>>(hs);
    router_logit_kernel<<<12, 256>>>(Wr, br);   // 96 warps = 8 batches x 12 heads
    router_topk_kernel<<<1, 32>>>();
    qkv_hmma_kernel<<<dim3(SEQ / 128, BATCH * NH), 256, QKV_SMEM>>>(bq, bk, bv);
    attn_hmma_kernel<<<dim3(SEQ / 128, BATCH * NH), 256, ATT_SMEM>>>();
    wo_hmma_kernel<<<dim3(SEQ / 128, HIDDEN / 128, BATCH), 256, WO_SMEM>>>(hs, bo, out);
    ln_kernel<<<BATCH * SEQ, 256>>>(out, lg, lb);
}

// round 10
// speedup vs baseline: 1.0102x; 1.0102x over previous
#include <cuda_runtime.h>
#include <cuda_bf16.h>
#include <cstdint>

#define BATCH  8
#define SEQ    1024
#define NH     12
#define HD     64
#define HIDDEN 768
#define KSEL   6

// ---------------- device scratch (no allocations allowed) ----------------
__device__ float g_mask[BATCH][NH];
__device__ float g_rsum[BATCH][8][HIDDEN];
__device__ float g_logits[BATCH][NH];
__device__ __align__(16) __nv_bfloat16 g_q16[(size_t)BATCH * NH * SEQ * HD];
__device__ __align__(16) __nv_bfloat16 g_k16[(size_t)BATCH * NH * SEQ * HD];
__device__ __align__(16) __nv_bfloat16 g_v16[(size_t)BATCH * NH * SEQ * HD];
__device__ __align__(16) __nv_bfloat16 g_hs16[(size_t)BATCH * SEQ * HIDDEN];
__device__ __align__(16) __nv_bfloat16 g_ctx16[(size_t)BATCH * SEQ * HIDDEN];
__device__ __align__(16) __nv_bfloat16 g_wt[4][(size_t)HIDDEN * HIDDEN]; // transposed: wt[c][k]=W[k][c]

// ---------------- helpers ----------------
__device__ __forceinline__ uint32_t smem_u32(const void* p) {
    uint32_t a;
    asm("{ .reg .u64 t; cvta.to.shared.u64 t, %1; cvt.u32.u64 %0, t; }" : "=r"(a) : "l"(p));
    return a;
}
#define SWZ(x) ((x) ^ (((x) >> 3) & 0x70))

__device__ __forceinline__ void cp16(uint32_t saddr, const void* g) {
    asm volatile("cp.async.cg.shared.global [%0], [%1], 16;" :: "r"(saddr), "l"(g));
}
#define CP_COMMIT() asm volatile("cp.async.commit_group;")
#define CP_WAIT0()  asm volatile("cp.async.wait_group 0;")

__device__ __forceinline__ void ldm_x4(uint32_t* r, uint32_t addr) {
    asm volatile("ldmatrix.sync.aligned.m8n8.x4.shared.b16 {%0,%1,%2,%3}, [%4];"
                 : "=r"(r[0]), "=r"(r[1]), "=r"(r[2]), "=r"(r[3]) : "r"(addr));
}
__device__ __forceinline__ void ldm_x4t(uint32_t* r, uint32_t addr) {
    asm volatile("ldmatrix.sync.aligned.m8n8.x4.trans.shared.b16 {%0,%1,%2,%3}, [%4];"
                 : "=r"(r[0]), "=r"(r[1]), "=r"(r[2]), "=r"(r[3]) : "r"(addr));
}
__device__ __forceinline__ void mma16816(float* c, const uint32_t* a, const uint32_t* b) {
    asm volatile(
        "mma.sync.aligned.m16n8k16.row.col.f32.bf16.bf16.f32 "
        "{%0,%1,%2,%3}, {%4,%5,%6,%7}, {%8,%9}, {%0,%1,%2,%3};"
        : "+f"(c[0]), "+f"(c[1]), "+f"(c[2]), "+f"(c[3])
        : "r"(a[0]), "r"(a[1]), "r"(a[2]), "r"(a[3]), "r"(b[0]), "r"(b[1]));
}
__device__ __forceinline__ uint32_t packbf2(float x, float y) {
    __nv_bfloat162 v = __floats2bfloat162_rn(x, y);
    return *(uint32_t*)&v;
}

// ---------------- weight convert (transpose + bf16) ----------------
__global__ void conv_wt_kernel(const float* __restrict__ W0, const float* __restrict__ W1,
                               const float* __restrict__ W2, const float* __restrict__ W3) {
    __shared__ float tile[32][33];
    int which = blockIdx.z;
    const float* W = which == 0 ? W0 : (which == 1 ? W1 : (which == 2 ? W2 : W3));
    int k0 = blockIdx.x * 32, c0 = blockIdx.y * 32;
    int tx = threadIdx.x, ty = threadIdx.y;  // 32 x 8
    #pragma unroll
    for (int j = 0; j < 32; j += 8)
        tile[ty + j][tx] = W[(size_t)(k0 + ty + j) * HIDDEN + c0 + tx];
    __syncthreads();
    __nv_bfloat16* wt = g_wt[which];
    #pragma unroll
    for (int j = 0; j < 32; j += 8)
        wt[(size_t)(c0 + ty + j) * HIDDEN + k0 + tx] = __float2bfloat16(tile[tx][ty + j]);
}

// ---------------- router stage 1 + hs bf16 conversion (fused) ------------
__global__ void router_sum_conv_kernel(const float* __restrict__ hs) {
    int b = blockIdx.x, chunk = blockIdx.y, t = threadIdx.x;
    const float* p = hs + ((size_t)b * SEQ + chunk * 128) * HIDDEN;
    for (int d = t; d < HIDDEN; d += 256) {
        float a0 = 0.f, a1 = 0.f, a2 = 0.f, a3 = 0.f;
        #pragma unroll 4
        for (int s = 0; s < 128; s += 4) {
            a0 += p[(size_t)(s + 0) * HIDDEN + d];
            a1 += p[(size_t)(s + 1) * HIDDEN + d];
            a2 += p[(size_t)(s + 2) * HIDDEN + d];
            a3 += p[(size_t)(s + 3) * HIDDEN + d];
        }
        g_rsum[b][chunk][d] = (a0 + a1) + (a2 + a3);
    }
    const float4* src = (const float4*)p;
    __nv_bfloat162* dst = (__nv_bfloat162*)(g_hs16 + ((size_t)(b * SEQ + chunk * 128)) * HIDDEN);
    const int N4 = 128 * HIDDEN / 4;
    for (int i = t; i < N4; i += 256) {
        float4 v = src[i];
        dst[2 * i + 0] = __floats2bfloat162_rn(v.x, v.y);
        dst[2 * i + 1] = __floats2bfloat162_rn(v.z, v.w);
    }
}

// one warp per (batch, head): 96 warps = 12 blocks x 256 threads, fp32
__global__ void router_logit_kernel(const float* __restrict__ Wr,
                                    const float* __restrict__ br) {
    int gw = (blockIdx.x * blockDim.x + threadIdx.x) >> 5;
    int lane = threadIdx.x & 31;
    int b = gw / NH, h = gw % NH;
    if (b >= BATCH) return;
    float acc0 = 0.f, acc1 = 0.f;
    #pragma unroll
    for (int i = 0; i < HIDDEN / 64; i++) {
        int d0 = i * 64 + lane;
        int d1 = d0 + 32;
        float s0 = 0.f, s1 = 0.f;
        #pragma unroll
        for (int c = 0; c < 8; c++) { s0 += g_rsum[b][c][d0]; s1 += g_rsum[b][c][d1]; }
        acc0 += s0 * Wr[d0 * NH + h];
        acc1 += s1 * Wr[d1 * NH + h];
    }
    float acc = acc0 + acc1;
    #pragma unroll
    for (int o = 16; o > 0; o >>= 1)
        acc += __shfl_xor_sync(0xFFFFFFFF, acc, o);
    if (lane == 0)
        g_logits[b][h] = acc / (float)SEQ + br[h];
}

__global__ void router_topk_kernel() {
    int b = threadIdx.x;
    if (b >= BATCH) return;
    float lg[NH];
    #pragma unroll
    for (int h = 0; h < NH; h++) lg[h] = g_logits[b][h];
    bool sel[NH];
    #pragma unroll
    for (int h = 0; h < NH; h++) sel[h] = false;
    for (int k = 0; k < KSEL; k++) {
        int best = -1; float bv = 0.f;
        for (int h = 0; h < NH; h++)
            if (!sel[h] && (best < 0 || lg[h] > bv)) { bv = lg[h]; best = h; }
        sel[best] = true;
    }
    for (int h = 0; h < NH; h++) g_mask[b][h] = sel[h] ? 1.f : 0.f;
}

// ---------------- QKV: HMMA bf16 GEMM (128s x 64n per CTA, sec=blockIdx.z) -
#define QKV_SMEM 49152

__global__ __launch_bounds__(256) void qkv_hmma_kernel(const float* __restrict__ bq,
                                                       const float* __restrict__ bk,
                                                       const float* __restrict__ bv) {
    int t = threadIdx.x, wid = t >> 5, lane = t & 31;
    int s0 = blockIdx.x * 128;
    int h = blockIdx.y % NH, b = blockIdx.y / NH;
    int sec = blockIdx.z;
    if (g_mask[b][h] == 0.f) return;

    extern __shared__ char dsm[];
    uint32_t sbA = smem_u32(dsm);           // 2 x 16384
    uint32_t sbB = sbA + 32768;             // 2 x 8192

    const __nv_bfloat16* Asrc = g_hs16 + ((size_t)(b * SEQ + s0)) * HIDDEN;
    const __nv_bfloat16* Bsrc = g_wt[sec] + ((size_t)h * 64) * HIDDEN;

    int m0 = (wid & 3) * 32, n0 = (wid >> 2) * 32;
    float acc[2][4][4];
    #pragma unroll
    for (int i = 0; i < 2; i++)
        #pragma unroll
        for (int j = 0; j < 4; j++)
            #pragma unroll
            for (int x = 0; x < 4; x++) acc[i][j][x] = 0.f;

    auto load_chunk = [&](int buf, int k0) {
        uint32_t ab = sbA + buf * 16384;
        #pragma unroll
        for (int i = 0; i < 4; i++) {
            int u = i * 256 + t, row = u >> 3, ch = u & 7;
            cp16(ab + SWZ(row * 128 + ch * 16), Asrc + (size_t)row * HIDDEN + k0 + ch * 8);
        }
        uint32_t bb = sbB + buf * 8192;
        #pragma unroll
        for (int i = 0; i < 2; i++) {
            int u = i * 256 + t, row = u >> 3, ch = u & 7;
            cp16(bb + SWZ(row * 128 + ch * 16), Bsrc + (size_t)row * HIDDEN + k0 + ch * 8);
        }
    };

    load_chunk(0, 0);
    CP_COMMIT();
    int cur = 0;
    const int NC = HIDDEN / 64;
    for (int c = 0; c < NC; c++) {
        CP_WAIT0();
        __syncthreads();
        if (c + 1 < NC) { load_chunk(cur ^ 1, (c + 1) * 64); CP_COMMIT(); }
        uint32_t aBase = sbA + cur * 16384;
        uint32_t bBase = sbB + cur * 8192;
        #pragma unroll
        for (int kk = 0; kk < 4; kk++) {
            int kb = kk * 32;
            uint32_t a[2][4], bf[2][4];
            #pragma unroll
            for (int mt = 0; mt < 2; mt++) {
                int row = m0 + mt * 16 + ((lane >> 3) & 1) * 8 + (lane & 7);
                int ko = kb + (lane >> 4) * 16;
                ldm_x4(a[mt], aBase + SWZ(row * 128 + ko));
            }
            #pragma unroll
            for (int hf = 0; hf < 2; hf++) {
                int row = n0 + hf * 16 + (lane >> 4) * 8 + (lane & 7);
                int ko = kb + ((lane >> 3) & 1) * 16;
                ldm_x4(bf[hf], bBase + SWZ(row * 128 + ko));
            }
            #pragma unroll
            for (int mt = 0; mt < 2; mt++)
                #pragma unroll
                for (int nt = 0; nt < 4; nt++)
                    mma16816(acc[mt][nt], a[mt], &bf[nt >> 1][(nt & 1) * 2]);
        }
        cur ^= 1;
    }

    const float* bias = sec == 0 ? bq : (sec == 1 ? bk : bv);
    __nv_bfloat16* base = sec == 0 ? g_q16 : (sec == 1 ? g_k16 : g_v16);
    __nv_bfloat16* dst = base + (((size_t)b * NH + h) * SEQ + s0) * HD;
    #pragma unroll
    for (int mt = 0; mt < 2; mt++)
        #pragma unroll
        for (int nt = 0; nt < 4; nt++) {
            int r = m0 + mt * 16 + (lane >> 2);
            int cc = n0 + nt * 8 + (lane & 3) * 2;
            float b0 = bias[h * 64 + cc], b1 = bias[h * 64 + cc + 1];
            *(__nv_bfloat162*)(dst + (size_t)r * HD + cc) =
                __floats2bfloat162_rn(acc[mt][nt][0] + b0, acc[mt][nt][1] + b1);
            *(__nv_bfloat162*)(dst + (size_t)(r + 8) * HD + cc) =
                __floats2bfloat162_rn(acc[mt][nt][2] + b0, acc[mt][nt][3] + b1);
        }
}

// ---------------- attention: HMMA flash (no max-shift; scores bounded) -----
#define ATT_SMEM 49152

__global__ __launch_bounds__(256, 2) void attn_hmma_kernel() {
    int b = blockIdx.y / NH, h = blockIdx.y % NH;
    if (g_mask[b][h] == 0.f) return;
    int t = threadIdx.x, wid = t >> 5, lane = t & 31;
    int s0 = blockIdx.x * 128;

    extern __shared__ char dsm[];
    uint32_t sQ = smem_u32(dsm);
    uint32_t sK = sQ + 16384;
    uint32_t sV = sQ + 32768;

    const __nv_bfloat16* qsrc = g_q16 + (((size_t)b * NH + h) * SEQ + s0) * HD;
    const __nv_bfloat16* ksrc = g_k16 + (((size_t)b * NH + h) * SEQ) * HD;
    const __nv_bfloat16* vsrc = g_v16 + (((size_t)b * NH + h) * SEQ) * HD;

    #pragma unroll
    for (int i = 0; i < 4; i++) {
        int u = i * 256 + t, row = u >> 3, ch = u & 7;
        cp16(sQ + SWZ(row * 128 + ch * 16), qsrc + (size_t)row * HD + ch * 8);
    }
    auto load_kv = [&](int buf, int kt) {
        #pragma unroll
        for (int i = 0; i < 2; i++) {
            int u = i * 256 + t, row = u >> 3, ch = u & 7;
            cp16(sK + buf * 8192 + SWZ(row * 128 + ch * 16),
                 ksrc + (size_t)(kt * 64 + row) * HD + ch * 8);
            cp16(sV + buf * 8192 + SWZ(row * 128 + ch * 16),
                 vsrc + (size_t)(kt * 64 + row) * HD + ch * 8);
        }
    };
    load_kv(0, 0);
    CP_COMMIT();

    int m0 = wid * 16;
    float o[8][4];
    #pragma unroll
    for (int i = 0; i < 8; i++)
        #pragma unroll
        for (int j = 0; j < 4; j++) o[i][j] = 0.f;
    float l0 = 0.f, l1 = 0.f;

    int rowA = m0 + ((lane >> 3) & 1) * 8 + (lane & 7);
    int koA  = (lane >> 4) * 16;
    int rowBb = (lane >> 4) * 8 + (lane & 7);
    int koB  = ((lane >> 3) & 1) * 16;
    int rowV = ((lane >> 3) & 1) * 8 + (lane & 7);
    int koV  = ((lane >> 4) & 1) * 16;

    int cur = 0;
    for (int kt = 0; kt < SEQ / 64; kt++) {
        CP_WAIT0();
        __syncthreads();
        if (kt + 1 < SEQ / 64) { load_kv(cur ^ 1, kt + 1); CP_COMMIT(); }

        uint32_t kBase = sK + cur * 8192;
        uint32_t vBase = sV + cur * 8192;

        float s[8][4];
        #pragma unroll
        for (int i = 0; i < 8; i++)
            #pragma unroll
            for (int j = 0; j < 4; j++) s[i][j] = 0.f;
        #pragma unroll
        for (int ds = 0; ds < 4; ds++) {
            uint32_t qa[4];
            ldm_x4(qa, sQ + SWZ(rowA * 128 + ds * 32 + koA));
            #pragma unroll
            for (int nf = 0; nf < 4; nf++) {
                uint32_t kb4[4];
                ldm_x4(kb4, kBase + SWZ((nf * 16 + rowBb) * 128 + ds * 32 + koB));
                mma16816(s[2 * nf + 0], qa, &kb4[0]);
                mma16816(s[2 * nf + 1], qa, &kb4[2]);
            }
        }
        uint32_t pa[4][4];
        #pragma unroll
        for (int nf = 0; nf < 8; nf++) {
            s[nf][0] = __expf(s[nf][0] * 0.125f);
            s[nf][1] = __expf(s[nf][1] * 0.125f);
            s[nf][2] = __expf(s[nf][2] * 0.125f);
            s[nf][3] = __expf(s[nf][3] * 0.125f);
            l0 += s[nf][0] + s[nf][1];
            l1 += s[nf][2] + s[nf][3];
        }
        #pragma unroll
        for (int ks = 0; ks < 4; ks++) {
            pa[ks][0] = packbf2(s[2 * ks][0],     s[2 * ks][1]);
            pa[ks][1] = packbf2(s[2 * ks][2],     s[2 * ks][3]);
            pa[ks][2] = packbf2(s[2 * ks + 1][0], s[2 * ks + 1][1]);
            pa[ks][3] = packbf2(s[2 * ks + 1][2], s[2 * ks + 1][3]);
        }
        #pragma unroll
        for (int ks = 0; ks < 4; ks++) {
            #pragma unroll
            for (int dh = 0; dh < 4; dh++) {
                uint32_t vb[4];
                ldm_x4t(vb, vBase + SWZ((ks * 16 + rowV) * 128 + dh * 32 + koV));
                mma16816(o[2 * dh + 0], pa[ks], &vb[0]);
                mma16816(o[2 * dh + 1], pa[ks], &vb[2]);
            }
        }
        cur ^= 1;
    }

    l0 += __shfl_xor_sync(0xFFFFFFFF, l0, 1);
    l0 += __shfl_xor_sync(0xFFFFFFFF, l0, 2);
    l1 += __shfl_xor_sync(0xFFFFFFFF, l1, 1);
    l1 += __shfl_xor_sync(0xFFFFFFFF, l1, 2);
    float inv0 = 1.f / l0, inv1 = 1.f / l1;

    int r0 = s0 + m0 + (lane >> 2);
    __nv_bfloat16* c0 = g_ctx16 + ((size_t)(b * SEQ + r0)) * HIDDEN + h * 64;
    __nv_bfloat16* c1 = c0 + (size_t)8 * HIDDEN;
    #pragma unroll
    for (int dn = 0; dn < 8; dn++) {
        int d = dn * 8 + (lane & 3) * 2;
        *(__nv_bfloat162*)(c0 + d) = __floats2bfloat162_rn(o[dn][0] * inv0, o[dn][1] * inv0);
        *(__nv_bfloat162*)(c1 + d) = __floats2bfloat162_rn(o[dn][2] * inv1, o[dn][3] * inv1);
    }
}

// ---------------- Wo: HMMA bf16, active-head K only, bias+residual fused ---
#define WO_SMEM 65536

__global__ __launch_bounds__(256) void wo_hmma_kernel(const float* __restrict__ hs,
                                                      const float* __restrict__ bo,
                                                      float* __restrict__ out) {
    int t = threadIdx.x, wid = t >> 5, lane = t & 31;
    int s0 = blockIdx.x * 128;
    int col0 = blockIdx.y * 128;
    int b = blockIdx.z;

    int act[KSEL]; int na = 0;
    #pragma unroll
    for (int h = 0; h < NH; h++)
        if (g_mask[b][h] != 0.f) { if (na < KSEL) act[na] = h; na++; }

    extern __shared__ char dsm[];
    uint32_t sbA = smem_u32(dsm);
    uint32_t sbB = sbA + 32768;

    int m0 = (wid & 3) * 32, n0 = (wid >> 2) * 64;
    float acc[2][8][4];
    #pragma unroll
    for (int i = 0; i < 2; i++)
        #pragma unroll
        for (int j = 0; j < 8; j++)
            #pragma unroll
            for (int x = 0; x < 4; x++) acc[i][j][x] = 0.f;

    auto load_chunk = [&](int buf, int h) {
        const __nv_bfloat16* Asrc = g_ctx16 + ((size_t)(b * SEQ + s0)) * HIDDEN + h * 64;
        uint32_t ab = sbA + buf * 16384;
        #pragma unroll
        for (int i = 0; i < 4; i++) {
            int u = i * 256 + t, row = u >> 3, ch = u & 7;
            cp16(ab + SWZ(row * 128 + ch * 16), Asrc + (size_t)row * HIDDEN + ch * 8);
        }
        const __nv_bfloat16* Bsrc = g_wt[3] + ((size_t)col0) * HIDDEN + h * 64;
        uint32_t bb = sbB + buf * 16384;
        #pragma unroll
        for (int i = 0; i < 4; i++) {
            int u = i * 256 + t, row = u >> 3, ch = u & 7;
            cp16(bb + SWZ(row * 128 + ch * 16), Bsrc + (size_t)row * HIDDEN + ch * 8);
        }
    };

    load_chunk(0, act[0]);
    CP_COMMIT();
    int cur = 0;
    for (int c = 0; c < KSEL; c++) {
        CP_WAIT0();
        __syncthreads();
        if (c + 1 < KSEL) { load_chunk(cur ^ 1, act[c + 1]); CP_COMMIT(); }
        uint32_t aBase = sbA + cur * 16384;
        uint32_t bBase = sbB + cur * 16384;
        #pragma unroll
        for (int kk = 0; kk < 4; kk++) {
            int kb = kk * 32;
            uint32_t a[2][4], bf[4][4];
            #pragma unroll
            for (int mt = 0; mt < 2; mt++) {
                int row = m0 + mt * 16 + ((lane >> 3) & 1) * 8 + (lane & 7);
                int ko = kb + (lane >> 4) * 16;
                ldm_x4(a[mt], aBase + SWZ(row * 128 + ko));
            }
            #pragma unroll
            for (int hf = 0; hf < 4; hf++) {
                int row = n0 + hf * 16 + (lane >> 4) * 8 + (lane & 7);
                int ko = kb + ((lane >> 3) & 1) * 16;
                ldm_x4(bf[hf], bBase + SWZ(row * 128 + ko));
            }
            #pragma unroll
            for (int mt = 0; mt < 2; mt++)
                #pragma unroll
                for (int nt = 0; nt < 8; nt++)
                    mma16816(acc[mt][nt], a[mt], &bf[nt >> 1][(nt & 1) * 2]);
        }
        cur ^= 1;
    }

    #pragma unroll
    for (int mt = 0; mt < 2; mt++)
        #pragma unroll
        for (int nt = 0; nt < 8; nt++) {
            int r = s0 + m0 + mt * 16 + (lane >> 2);
            int cc = col0 + n0 + nt * 8 + (lane & 3) * 2;
            float b0 = bo[cc], b1 = bo[cc + 1];
            float2 r0 = *(const float2*)(hs + ((size_t)(b * SEQ + r)) * HIDDEN + cc);
            float2 r1 = *(const float2*)(hs + ((size_t)(b * SEQ + r + 8)) * HIDDEN + cc);
            float2 v0 = make_float2(acc[mt][nt][0] + b0 + r0.x, acc[mt][nt][1] + b1 + r0.y);
            float2 v1 = make_float2(acc[mt][nt][2] + b0 + r1.x, acc[mt][nt][3] + b1 + r1.y);
            *(float2*)(out + ((size_t)(b * SEQ + r)) * HIDDEN + cc) = v0;
            *(float2*)(out + ((size_t)(b * SEQ + r + 8)) * HIDDEN + cc) = v1;
        }
}

// ---------------- LayerNorm in-place ----------------
__global__ void ln_kernel(float* __restrict__ x, const float* __restrict__ g,
                          const float* __restrict__ bb) {
    int row = blockIdx.x;
    int t = threadIdx.x;
    float* p = x + (size_t)row * HIDDEN;
    float v0 = p[t], v1 = p[t + 256], v2 = p[t + 512];
    __shared__ float red[256];
    red[t] = v0 + v1 + v2;
    __syncthreads();
    for (int o = 128; o > 0; o >>= 1) { if (t < o) red[t] += red[t + o]; __syncthreads(); }
    float mu = red[0] * (1.f / HIDDEN);
    __syncthreads();
    float d0 = v0 - mu, d1 = v1 - mu, d2 = v2 - mu;
    red[t] = d0 * d0 + d1 * d1 + d2 * d2;
    __syncthreads();
    for (int o = 128; o > 0; o >>= 1) { if (t < o) red[t] += red[t + o]; __syncthreads(); }
    float rs = rsqrtf(red[0] * (1.f / HIDDEN) + 1e-12f);
    p[t]       = d0 * rs * g[t]       + bb[t];
    p[t + 256] = d1 * rs * g[t + 256] + bb[t + 256];
    p[t + 512] = d2 * rs * g[t + 512] + bb[t + 512];
}

// ---------------------------------------------------------------------------
extern "C" void kernel_launch(void* const* d_in, const int* in_sizes, int n_in,
                              void* d_out, int out_size) {
    (void)in_sizes; (void)n_in; (void)out_size;
    const float* hs = (const float*)d_in[0];
    const float* Wq = (const float*)d_in[1];
    const float* bq = (const float*)d_in[2];
    const float* Wk = (const float*)d_in[3];
    const float* bk = (const float*)d_in[4];
    const float* Wv = (const float*)d_in[5];
    const float* bv = (const float*)d_in[6];
    const float* Wr = (const float*)d_in[7];
    const float* br = (const float*)d_in[8];
    const float* Wo = (const float*)d_in[9];
    const float* bo = (const float*)d_in[10];
    const float* lg = (const float*)d_in[11];
    const float* lb = (const float*)d_in[12];
    float* out = (float*)d_out;

    cudaFuncSetAttribute(qkv_hmma_kernel, cudaFuncAttributeMaxDynamicSharedMemorySize, QKV_SMEM);
    cudaFuncSetAttribute(attn_hmma_kernel, cudaFuncAttributeMaxDynamicSharedMemorySize, ATT_SMEM);
    cudaFuncSetAttribute(wo_hmma_kernel,  cudaFuncAttributeMaxDynamicSharedMemorySize, WO_SMEM);

    conv_wt_kernel<<<dim3(24, 24, 4), dim3(32, 8)>>>(Wq, Wk, Wv, Wo);
    router_sum_conv_kernel<<<dim3(BATCH, 8), 256>>>(hs);
    router_logit_kernel<<<12, 256>>>(Wr, br);   // 96 warps = 8 batches x 12 heads
    router_topk_kernel<<<1, 32>>>();
    qkv_hmma_kernel<<<dim3(SEQ / 128, BATCH * NH, 3), 256, QKV_SMEM>>>(bq, bk, bv);
    attn_hmma_kernel<<<dim3(SEQ / 128, BATCH * NH), 256, ATT_SMEM>>>();
    wo_hmma_kernel<<<dim3(SEQ / 128, HIDDEN / 128, BATCH), 256, WO_SMEM>>>(hs, bo, out);
    ln_kernel<<<BATCH * SEQ, 256>>>(out, lg, lb);
}

// round 11
// speedup vs baseline: 1.1783x; 1.1665x over previous
#include <cuda_runtime.h>
#include <cuda_bf16.h>
#include <cstdint>

#define BATCH  8
#define SEQ    1024
#define NH     12
#define HD     64
#define HIDDEN 768
#define KSEL   6

// ---------------- device scratch (no allocations allowed) ----------------
__device__ float g_mask[BATCH][NH];
__device__ float g_rsum[BATCH][64][HIDDEN];
__device__ __align__(16) __nv_bfloat16 g_q16[(size_t)BATCH * NH * SEQ * HD];
__device__ __align__(16) __nv_bfloat16 g_k16[(size_t)BATCH * NH * SEQ * HD];
__device__ __align__(16) __nv_bfloat16 g_v16[(size_t)BATCH * NH * SEQ * HD];
__device__ __align__(16) __nv_bfloat16 g_hs16[(size_t)BATCH * SEQ * HIDDEN];
__device__ __align__(16) __nv_bfloat16 g_ctx16[(size_t)BATCH * SEQ * HIDDEN];
__device__ __align__(16) __nv_bfloat16 g_wt[4][(size_t)HIDDEN * HIDDEN]; // transposed: wt[c][k]=W[k][c]

// ---------------- helpers ----------------
__device__ __forceinline__ uint32_t smem_u32(const void* p) {
    uint32_t a;
    asm("{ .reg .u64 t; cvta.to.shared.u64 t, %1; cvt.u32.u64 %0, t; }" : "=r"(a) : "l"(p));
    return a;
}
#define SWZ(x) ((x) ^ (((x) >> 3) & 0x70))

__device__ __forceinline__ void cp16(uint32_t saddr, const void* g) {
    asm volatile("cp.async.cg.shared.global [%0], [%1], 16;" :: "r"(saddr), "l"(g));
}
#define CP_COMMIT() asm volatile("cp.async.commit_group;")
#define CP_WAIT0()  asm volatile("cp.async.wait_group 0;")

__device__ __forceinline__ void ldm_x4(uint32_t* r, uint32_t addr) {
    asm volatile("ldmatrix.sync.aligned.m8n8.x4.shared.b16 {%0,%1,%2,%3}, [%4];"
                 : "=r"(r[0]), "=r"(r[1]), "=r"(r[2]), "=r"(r[3]) : "r"(addr));
}
__device__ __forceinline__ void ldm_x4t(uint32_t* r, uint32_t addr) {
    asm volatile("ldmatrix.sync.aligned.m8n8.x4.trans.shared.b16 {%0,%1,%2,%3}, [%4];"
                 : "=r"(r[0]), "=r"(r[1]), "=r"(r[2]), "=r"(r[3]) : "r"(addr));
}
__device__ __forceinline__ void mma16816(float* c, const uint32_t* a, const uint32_t* b) {
    asm volatile(
        "mma.sync.aligned.m16n8k16.row.col.f32.bf16.bf16.f32 "
        "{%0,%1,%2,%3}, {%4,%5,%6,%7}, {%8,%9}, {%0,%1,%2,%3};"
        : "+f"(c[0]), "+f"(c[1]), "+f"(c[2]), "+f"(c[3])
        : "r"(a[0]), "r"(a[1]), "r"(a[2]), "r"(a[3]), "r"(b[0]), "r"(b[1]));
}
__device__ __forceinline__ uint32_t packbf2(float x, float y) {
    __nv_bfloat162 v = __floats2bfloat162_rn(x, y);
    return *(uint32_t*)&v;
}

// ---------------- weight convert (transpose + bf16) ----------------
__global__ void conv_wt_kernel(const float* __restrict__ W0, const float* __restrict__ W1,
                               const float* __restrict__ W2, const float* __restrict__ W3) {
    __shared__ float tile[32][33];
    int which = blockIdx.z;
    const float* W = which == 0 ? W0 : (which == 1 ? W1 : (which == 2 ? W2 : W3));
    int k0 = blockIdx.x * 32, c0 = blockIdx.y * 32;
    int tx = threadIdx.x, ty = threadIdx.y;  // 32 x 8
    #pragma unroll
    for (int j = 0; j < 32; j += 8)
        tile[ty + j][tx] = W[(size_t)(k0 + ty + j) * HIDDEN + c0 + tx];
    __syncthreads();
    __nv_bfloat16* wt = g_wt[which];
    #pragma unroll
    for (int j = 0; j < 32; j += 8)
        wt[(size_t)(c0 + ty + j) * HIDDEN + k0 + tx] = __float2bfloat16(tile[tx][ty + j]);
}

// ---- hs bf16 conversion + 16-row column partial sums (512 CTAs) ----------
__global__ __launch_bounds__(192) void conv_sum_kernel(const float* __restrict__ hs) {
    int b = blockIdx.x, chunk = blockIdx.y, t = threadIdx.x;  // 192 threads, 1 float4-col each
    const float4* src = (const float4*)(hs + ((size_t)(b * SEQ + chunk * 16)) * HIDDEN);
    __nv_bfloat162* dst = (__nv_bfloat162*)(g_hs16 + ((size_t)(b * SEQ + chunk * 16)) * HIDDEN);
    float4 acc = make_float4(0.f, 0.f, 0.f, 0.f);
    #pragma unroll
    for (int r = 0; r < 16; r++) {
        float4 v = src[r * 192 + t];
        acc.x += v.x; acc.y += v.y; acc.z += v.z; acc.w += v.w;
        dst[2 * (r * 192 + t) + 0] = __floats2bfloat162_rn(v.x, v.y);
        dst[2 * (r * 192 + t) + 1] = __floats2bfloat162_rn(v.z, v.w);
    }
    *(float4*)&g_rsum[b][chunk][4 * t] = acc;
}

// ---- router: chunk-reduce + warp-per-head logits + topk, one launch ------
__global__ void router_kernel(const float* __restrict__ Wr, const float* __restrict__ br) {
    int b = blockIdx.x, t = threadIdx.x;
    __shared__ float ssum[HIDDEN];
    __shared__ float slog[NH];
    for (int d = t; d < HIDDEN; d += 256) {
        float a0 = 0.f, a1 = 0.f, a2 = 0.f, a3 = 0.f;
        #pragma unroll 4
        for (int c = 0; c < 64; c += 4) {
            a0 += g_rsum[b][c + 0][d];
            a1 += g_rsum[b][c + 1][d];
            a2 += g_rsum[b][c + 2][d];
            a3 += g_rsum[b][c + 3][d];
        }
        ssum[d] = (a0 + a1) + (a2 + a3);
    }
    __syncthreads();
    int wid = t >> 5, lane = t & 31;
    for (int h = wid; h < NH; h += 8) {
        float acc = 0.f;
        #pragma unroll
        for (int i = 0; i < HIDDEN / 32; i++) {
            int d = i * 32 + lane;
            acc += ssum[d] * Wr[d * NH + h];
        }
        #pragma unroll
        for (int o = 16; o > 0; o >>= 1)
            acc += __shfl_xor_sync(0xFFFFFFFF, acc, o);
        if (lane == 0) slog[h] = acc / (float)SEQ + br[h];
    }
    __syncthreads();
    if (t == 0) {
        bool sel[NH];
        #pragma unroll
        for (int h = 0; h < NH; h++) sel[h] = false;
        for (int k = 0; k < KSEL; k++) {
            int best = -1; float bv = 0.f;
            for (int h = 0; h < NH; h++)
                if (!sel[h] && (best < 0 || slog[h] > bv)) { bv = slog[h]; best = h; }
            sel[best] = true;
        }
        for (int h = 0; h < NH; h++) g_mask[b][h] = sel[h] ? 1.f : 0.f;
    }
}

// ---------------- QKV: HMMA bf16 GEMM (128s x 64n per CTA, sec=blockIdx.z) -
#define QKV_SMEM 49152

__global__ __launch_bounds__(256) void qkv_hmma_kernel(const float* __restrict__ bq,
                                                       const float* __restrict__ bk,
                                                       const float* __restrict__ bv) {
    int t = threadIdx.x, wid = t >> 5, lane = t & 31;
    int s0 = blockIdx.x * 128;
    int h = blockIdx.y % NH, b = blockIdx.y / NH;
    int sec = blockIdx.z;
    if (g_mask[b][h] == 0.f) return;

    extern __shared__ char dsm[];
    uint32_t sbA = smem_u32(dsm);           // 2 x 16384
    uint32_t sbB = sbA + 32768;             // 2 x 8192

    const __nv_bfloat16* Asrc = g_hs16 + ((size_t)(b * SEQ + s0)) * HIDDEN;
    const __nv_bfloat16* Bsrc = g_wt[sec] + ((size_t)h * 64) * HIDDEN;

    int m0 = (wid & 3) * 32, n0 = (wid >> 2) * 32;
    float acc[2][4][4];
    #pragma unroll
    for (int i = 0; i < 2; i++)
        #pragma unroll
        for (int j = 0; j < 4; j++)
            #pragma unroll
            for (int x = 0; x < 4; x++) acc[i][j][x] = 0.f;

    auto load_chunk = [&](int buf, int k0) {
        uint32_t ab = sbA + buf * 16384;
        #pragma unroll
        for (int i = 0; i < 4; i++) {
            int u = i * 256 + t, row = u >> 3, ch = u & 7;
            cp16(ab + SWZ(row * 128 + ch * 16), Asrc + (size_t)row * HIDDEN + k0 + ch * 8);
        }
        uint32_t bb = sbB + buf * 8192;
        #pragma unroll
        for (int i = 0; i < 2; i++) {
            int u = i * 256 + t, row = u >> 3, ch = u & 7;
            cp16(bb + SWZ(row * 128 + ch * 16), Bsrc + (size_t)row * HIDDEN + k0 + ch * 8);
        }
    };

    load_chunk(0, 0);
    CP_COMMIT();
    int cur = 0;
    const int NC = HIDDEN / 64;
    for (int c = 0; c < NC; c++) {
        CP_WAIT0();
        __syncthreads();
        if (c + 1 < NC) { load_chunk(cur ^ 1, (c + 1) * 64); CP_COMMIT(); }
        uint32_t aBase = sbA + cur * 16384;
        uint32_t bBase = sbB + cur * 8192;
        #pragma unroll
        for (int kk = 0; kk < 4; kk++) {
            int kb = kk * 32;
            uint32_t a[2][4], bf[2][4];
            #pragma unroll
            for (int mt = 0; mt < 2; mt++) {
                int row = m0 + mt * 16 + ((lane >> 3) & 1) * 8 + (lane & 7);
                int ko = kb + (lane >> 4) * 16;
                ldm_x4(a[mt], aBase + SWZ(row * 128 + ko));
            }
            #pragma unroll
            for (int hf = 0; hf < 2; hf++) {
                int row = n0 + hf * 16 + (lane >> 4) * 8 + (lane & 7);
                int ko = kb + ((lane >> 3) & 1) * 16;
                ldm_x4(bf[hf], bBase + SWZ(row * 128 + ko));
            }
            #pragma unroll
            for (int mt = 0; mt < 2; mt++)
                #pragma unroll
                for (int nt = 0; nt < 4; nt++)
                    mma16816(acc[mt][nt], a[mt], &bf[nt >> 1][(nt & 1) * 2]);
        }
        cur ^= 1;
    }

    const float* bias = sec == 0 ? bq : (sec == 1 ? bk : bv);
    __nv_bfloat16* base = sec == 0 ? g_q16 : (sec == 1 ? g_k16 : g_v16);
    __nv_bfloat16* dst = base + (((size_t)b * NH + h) * SEQ + s0) * HD;
    #pragma unroll
    for (int mt = 0; mt < 2; mt++)
        #pragma unroll
        for (int nt = 0; nt < 4; nt++) {
            int r = m0 + mt * 16 + (lane >> 2);
            int cc = n0 + nt * 8 + (lane & 3) * 2;
            float b0 = bias[h * 64 + cc], b1 = bias[h * 64 + cc + 1];
            *(__nv_bfloat162*)(dst + (size_t)r * HD + cc) =
                __floats2bfloat162_rn(acc[mt][nt][0] + b0, acc[mt][nt][1] + b1);
            *(__nv_bfloat162*)(dst + (size_t)(r + 8) * HD + cc) =
                __floats2bfloat162_rn(acc[mt][nt][2] + b0, acc[mt][nt][3] + b1);
        }
}

// ---------------- attention: HMMA flash (no max-shift; scores bounded) -----
#define ATT_SMEM 49152

__global__ __launch_bounds__(256, 2) void attn_hmma_kernel() {
    int b = blockIdx.y / NH, h = blockIdx.y % NH;
    if (g_mask[b][h] == 0.f) return;
    int t = threadIdx.x, wid = t >> 5, lane = t & 31;
    int s0 = blockIdx.x * 128;

    extern __shared__ char dsm[];
    uint32_t sQ = smem_u32(dsm);
    uint32_t sK = sQ + 16384;
    uint32_t sV = sQ + 32768;

    const __nv_bfloat16* qsrc = g_q16 + (((size_t)b * NH + h) * SEQ + s0) * HD;
    const __nv_bfloat16* ksrc = g_k16 + (((size_t)b * NH + h) * SEQ) * HD;
    const __nv_bfloat16* vsrc = g_v16 + (((size_t)b * NH + h) * SEQ) * HD;

    #pragma unroll
    for (int i = 0; i < 4; i++) {
        int u = i * 256 + t, row = u >> 3, ch = u & 7;
        cp16(sQ + SWZ(row * 128 + ch * 16), qsrc + (size_t)row * HD + ch * 8);
    }
    auto load_kv = [&](int buf, int kt) {
        #pragma unroll
        for (int i = 0; i < 2; i++) {
            int u = i * 256 + t, row = u >> 3, ch = u & 7;
            cp16(sK + buf * 8192 + SWZ(row * 128 + ch * 16),
                 ksrc + (size_t)(kt * 64 + row) * HD + ch * 8);
            cp16(sV + buf * 8192 + SWZ(row * 128 + ch * 16),
                 vsrc + (size_t)(kt * 64 + row) * HD + ch * 8);
        }
    };
    load_kv(0, 0);
    CP_COMMIT();

    int m0 = wid * 16;
    float o[8][4];
    #pragma unroll
    for (int i = 0; i < 8; i++)
        #pragma unroll
        for (int j = 0; j < 4; j++) o[i][j] = 0.f;
    float l0 = 0.f, l1 = 0.f;

    int rowA = m0 + ((lane >> 3) & 1) * 8 + (lane & 7);
    int koA  = (lane >> 4) * 16;
    int rowBb = (lane >> 4) * 8 + (lane & 7);
    int koB  = ((lane >> 3) & 1) * 16;
    int rowV = ((lane >> 3) & 1) * 8 + (lane & 7);
    int koV  = ((lane >> 4) & 1) * 16;

    int cur = 0;
    for (int kt = 0; kt < SEQ / 64; kt++) {
        CP_WAIT0();
        __syncthreads();
        if (kt + 1 < SEQ / 64) { load_kv(cur ^ 1, kt + 1); CP_COMMIT(); }

        uint32_t kBase = sK + cur * 8192;
        uint32_t vBase = sV + cur * 8192;

        float s[8][4];
        #pragma unroll
        for (int i = 0; i < 8; i++)
            #pragma unroll
            for (int j = 0; j < 4; j++) s[i][j] = 0.f;
        #pragma unroll
        for (int ds = 0; ds < 4; ds++) {
            uint32_t qa[4];
            ldm_x4(qa, sQ + SWZ(rowA * 128 + ds * 32 + koA));
            #pragma unroll
            for (int nf = 0; nf < 4; nf++) {
                uint32_t kb4[4];
                ldm_x4(kb4, kBase + SWZ((nf * 16 + rowBb) * 128 + ds * 32 + koB));
                mma16816(s[2 * nf + 0], qa, &kb4[0]);
                mma16816(s[2 * nf + 1], qa, &kb4[2]);
            }
        }
        uint32_t pa[4][4];
        #pragma unroll
        for (int nf = 0; nf < 8; nf++) {
            s[nf][0] = __expf(s[nf][0] * 0.125f);
            s[nf][1] = __expf(s[nf][1] * 0.125f);
            s[nf][2] = __expf(s[nf][2] * 0.125f);
            s[nf][3] = __expf(s[nf][3] * 0.125f);
            l0 += s[nf][0] + s[nf][1];
            l1 += s[nf][2] + s[nf][3];
        }
        #pragma unroll
        for (int ks = 0; ks < 4; ks++) {
            pa[ks][0] = packbf2(s[2 * ks][0],     s[2 * ks][1]);
            pa[ks][1] = packbf2(s[2 * ks][2],     s[2 * ks][3]);
            pa[ks][2] = packbf2(s[2 * ks + 1][0], s[2 * ks + 1][1]);
            pa[ks][3] = packbf2(s[2 * ks + 1][2], s[2 * ks + 1][3]);
        }
        #pragma unroll
        for (int ks = 0; ks < 4; ks++) {
            #pragma unroll
            for (int dh = 0; dh < 4; dh++) {
                uint32_t vb[4];
                ldm_x4t(vb, vBase + SWZ((ks * 16 + rowV) * 128 + dh * 32 + koV));
                mma16816(o[2 * dh + 0], pa[ks], &vb[0]);
                mma16816(o[2 * dh + 1], pa[ks], &vb[2]);
            }
        }
        cur ^= 1;
    }

    l0 += __shfl_xor_sync(0xFFFFFFFF, l0, 1);
    l0 += __shfl_xor_sync(0xFFFFFFFF, l0, 2);
    l1 += __shfl_xor_sync(0xFFFFFFFF, l1, 1);
    l1 += __shfl_xor_sync(0xFFFFFFFF, l1, 2);
    float inv0 = 1.f / l0, inv1 = 1.f / l1;

    int r0 = s0 + m0 + (lane >> 2);
    __nv_bfloat16* c0 = g_ctx16 + ((size_t)(b * SEQ + r0)) * HIDDEN + h * 64;
    __nv_bfloat16* c1 = c0 + (size_t)8 * HIDDEN;
    #pragma unroll
    for (int dn = 0; dn < 8; dn++) {
        int d = dn * 8 + (lane & 3) * 2;
        *(__nv_bfloat162*)(c0 + d) = __floats2bfloat162_rn(o[dn][0] * inv0, o[dn][1] * inv0);
        *(__nv_bfloat162*)(c1 + d) = __floats2bfloat162_rn(o[dn][2] * inv1, o[dn][3] * inv1);
    }
}

// ---------------- Wo: HMMA bf16, active-head K only, bias+residual fused ---
#define WO_SMEM 65536

__global__ __launch_bounds__(256) void wo_hmma_kernel(const float* __restrict__ hs,
                                                      const float* __restrict__ bo,
                                                      float* __restrict__ out) {
    int t = threadIdx.x, wid = t >> 5, lane = t & 31;
    int s0 = blockIdx.x * 128;
    int col0 = blockIdx.y * 128;
    int b = blockIdx.z;

    int act[KSEL]; int na = 0;
    #pragma unroll
    for (int h = 0; h < NH; h++)
        if (g_mask[b][h] != 0.f) { if (na < KSEL) act[na] = h; na++; }

    extern __shared__ char dsm[];
    uint32_t sbA = smem_u32(dsm);
    uint32_t sbB = sbA + 32768;

    int m0 = (wid & 3) * 32, n0 = (wid >> 2) * 64;
    float acc[2][8][4];
    #pragma unroll
    for (int i = 0; i < 2; i++)
        #pragma unroll
        for (int j = 0; j < 8; j++)
            #pragma unroll
            for (int x = 0; x < 4; x++) acc[i][j][x] = 0.f;

    auto load_chunk = [&](int buf, int h) {
        const __nv_bfloat16* Asrc = g_ctx16 + ((size_t)(b * SEQ + s0)) * HIDDEN + h * 64;
        uint32_t ab = sbA + buf * 16384;
        #pragma unroll
        for (int i = 0; i < 4; i++) {
            int u = i * 256 + t, row = u >> 3, ch = u & 7;
            cp16(ab + SWZ(row * 128 + ch * 16), Asrc + (size_t)row * HIDDEN + ch * 8);
        }
        const __nv_bfloat16* Bsrc = g_wt[3] + ((size_t)col0) * HIDDEN + h * 64;
        uint32_t bb = sbB + buf * 16384;
        #pragma unroll
        for (int i = 0; i < 4; i++) {
            int u = i * 256 + t, row = u >> 3, ch = u & 7;
            cp16(bb + SWZ(row * 128 + ch * 16), Bsrc + (size_t)row * HIDDEN + ch * 8);
        }
    };

    load_chunk(0, act[0]);
    CP_COMMIT();
    int cur = 0;
    for (int c = 0; c < KSEL; c++) {
        CP_WAIT0();
        __syncthreads();
        if (c + 1 < KSEL) { load_chunk(cur ^ 1, act[c + 1]); CP_COMMIT(); }
        uint32_t aBase = sbA + cur * 16384;
        uint32_t bBase = sbB + cur * 16384;
        #pragma unroll
        for (int kk = 0; kk < 4; kk++) {
            int kb = kk * 32;
            uint32_t a[2][4], bf[4][4];
            #pragma unroll
            for (int mt = 0; mt < 2; mt++) {
                int row = m0 + mt * 16 + ((lane >> 3) & 1) * 8 + (lane & 7);
                int ko = kb + (lane >> 4) * 16;
                ldm_x4(a[mt], aBase + SWZ(row * 128 + ko));
            }
            #pragma unroll
            for (int hf = 0; hf < 4; hf++) {
                int row = n0 + hf * 16 + (lane >> 4) * 8 + (lane & 7);
                int ko = kb + ((lane >> 3) & 1) * 16;
                ldm_x4(bf[hf], bBase + SWZ(row * 128 + ko));
            }
            #pragma unroll
            for (int mt = 0; mt < 2; mt++)
                #pragma unroll
                for (int nt = 0; nt < 8; nt++)
                    mma16816(acc[mt][nt], a[mt], &bf[nt >> 1][(nt & 1) * 2]);
        }
        cur ^= 1;
    }

    #pragma unroll
    for (int mt = 0; mt < 2; mt++)
        #pragma unroll
        for (int nt = 0; nt < 8; nt++) {
            int r = s0 + m0 + mt * 16 + (lane >> 2);
            int cc = col0 + n0 + nt * 8 + (lane & 3) * 2;
            float b0 = bo[cc], b1 = bo[cc + 1];
            float2 r0 = *(const float2*)(hs + ((size_t)(b * SEQ + r)) * HIDDEN + cc);
            float2 r1 = *(const float2*)(hs + ((size_t)(b * SEQ + r + 8)) * HIDDEN + cc);
            float2 v0 = make_float2(acc[mt][nt][0] + b0 + r0.x, acc[mt][nt][1] + b1 + r0.y);
            float2 v1 = make_float2(acc[mt][nt][2] + b0 + r1.x, acc[mt][nt][3] + b1 + r1.y);
            *(float2*)(out + ((size_t)(b * SEQ + r)) * HIDDEN + cc) = v0;
            *(float2*)(out + ((size_t)(b * SEQ + r + 8)) * HIDDEN + cc) = v1;
        }
}

// ---------------- LayerNorm in-place ----------------
__global__ void ln_kernel(float* __restrict__ x, const float* __restrict__ g,
                          const float* __restrict__ bb) {
    int row = blockIdx.x;
    int t = threadIdx.x;
    float* p = x + (size_t)row * HIDDEN;
    float v0 = p[t], v1 = p[t + 256], v2 = p[t + 512];
    __shared__ float red[256];
    red[t] = v0 + v1 + v2;
    __syncthreads();
    for (int o = 128; o > 0; o >>= 1) { if (t < o) red[t] += red[t + o]; __syncthreads(); }
    float mu = red[0] * (1.f / HIDDEN);
    __syncthreads();
    float d0 = v0 - mu, d1 = v1 - mu, d2 = v2 - mu;
    red[t] = d0 * d0 + d1 * d1 + d2 * d2;
    __syncthreads();
    for (int o = 128; o > 0; o >>= 1) { if (t < o) red[t] += red[t + o]; __syncthreads(); }
    float rs = rsqrtf(red[0] * (1.f / HIDDEN) + 1e-12f);
    p[t]       = d0 * rs * g[t]       + bb[t];
    p[t + 256] = d1 * rs * g[t + 256] + bb[t + 256];
    p[t + 512] = d2 * rs * g[t + 512] + bb[t + 512];
}

// ---------------------------------------------------------------------------
extern "C" void kernel_launch(void* const* d_in, const int* in_sizes, int n_in,
                              void* d_out, int out_size) {
    (void)in_sizes; (void)n_in; (void)out_size;
    const float* hs = (const float*)d_in[0];
    const float* Wq = (const float*)d_in[1];
    const float* bq = (const float*)d_in[2];
    const float* Wk = (const float*)d_in[3];
    const float* bk = (const float*)d_in[4];
    const float* Wv = (const float*)d_in[5];
    const float* bv = (const float*)d_in[6];
    const float* Wr = (const float*)d_in[7];
    const float* br = (const float*)d_in[8];
    const float* Wo = (const float*)d_in[9];
    const float* bo = (const float*)d_in[10];
    const float* lg = (const float*)d_in[11];
    const float* lb = (const float*)d_in[12];
    float* out = (float*)d_out;

    cudaFuncSetAttribute(qkv_hmma_kernel, cudaFuncAttributeMaxDynamicSharedMemorySize, QKV_SMEM);
    cudaFuncSetAttribute(attn_hmma_kernel, cudaFuncAttributeMaxDynamicSharedMemorySize, ATT_SMEM);
    cudaFuncSetAttribute(wo_hmma_kernel,  cudaFuncAttributeMaxDynamicSharedMemorySize, WO_SMEM);

    conv_wt_kernel<<<dim3(24, 24, 4), dim3(32, 8)>>>(Wq, Wk, Wv, Wo);
    conv_sum_kernel<<<dim3(BATCH, 64), 192>>>(hs);
    router_kernel<<<BATCH, 256>>>(Wr, br);
    qkv_hmma_kernel<<<dim3(SEQ / 128, BATCH * NH, 3), 256, QKV_SMEM>>>(bq, bk, bv);
    attn_hmma_kernel<<<dim3(SEQ / 128, BATCH * NH), 256, ATT_SMEM>>>();
    wo_hmma_kernel<<<dim3(SEQ / 128, HIDDEN / 128, BATCH), 256, WO_SMEM>>>(hs, bo, out);
    ln_kernel<<<BATCH * SEQ, 256>>>(out, lg, lb);
}

// round 12
// speedup vs baseline: 1.1897x; 1.0096x over previous
#include <cuda_runtime.h>
#include <cuda_bf16.h>
#include <cstdint>

#define BATCH  8
#define SEQ    1024
#define NH     12
#define HD     64
#define HIDDEN 768
#define KSEL   6

// ---------------- device scratch (no allocations allowed) ----------------
__device__ float g_mask[BATCH][NH];
__device__ float g_rsum[BATCH][64][HIDDEN];
__device__ __align__(16) __nv_bfloat16 g_q16[(size_t)BATCH * NH * SEQ * HD];
__device__ __align__(16) __nv_bfloat16 g_k16[(size_t)BATCH * NH * SEQ * HD];
__device__ __align__(16) __nv_bfloat16 g_v16[(size_t)BATCH * NH * SEQ * HD];
__device__ __align__(16) __nv_bfloat16 g_hs16[(size_t)BATCH * SEQ * HIDDEN];
__device__ __align__(16) __nv_bfloat16 g_ctx16[(size_t)BATCH * SEQ * HIDDEN];
__device__ __align__(16) __nv_bfloat16 g_wt[4][(size_t)HIDDEN * HIDDEN]; // transposed: wt[c][k]=W[k][c]

// ---------------- helpers ----------------
__device__ __forceinline__ uint32_t smem_u32(const void* p) {
    uint32_t a;
    asm("{ .reg .u64 t; cvta.to.shared.u64 t, %1; cvt.u32.u64 %0, t; }" : "=r"(a) : "l"(p));
    return a;
}
#define SWZ(x) ((x) ^ (((x) >> 3) & 0x70))

__device__ __forceinline__ void cp16(uint32_t saddr, const void* g) {
    asm volatile("cp.async.cg.shared.global [%0], [%1], 16;" :: "r"(saddr), "l"(g));
}
#define CP_COMMIT() asm volatile("cp.async.commit_group;")
#define CP_WAIT0()  asm volatile("cp.async.wait_group 0;")

__device__ __forceinline__ void ldm_x4(uint32_t* r, uint32_t addr) {
    asm volatile("ldmatrix.sync.aligned.m8n8.x4.shared.b16 {%0,%1,%2,%3}, [%4];"
                 : "=r"(r[0]), "=r"(r[1]), "=r"(r[2]), "=r"(r[3]) : "r"(addr));
}
__device__ __forceinline__ void ldm_x4t(uint32_t* r, uint32_t addr) {
    asm volatile("ldmatrix.sync.aligned.m8n8.x4.trans.shared.b16 {%0,%1,%2,%3}, [%4];"
                 : "=r"(r[0]), "=r"(r[1]), "=r"(r[2]), "=r"(r[3]) : "r"(addr));
}
__device__ __forceinline__ void mma16816(float* c, const uint32_t* a, const uint32_t* b) {
    asm volatile(
        "mma.sync.aligned.m16n8k16.row.col.f32.bf16.bf16.f32 "
        "{%0,%1,%2,%3}, {%4,%5,%6,%7}, {%8,%9}, {%0,%1,%2,%3};"
        : "+f"(c[0]), "+f"(c[1]), "+f"(c[2]), "+f"(c[3])
        : "r"(a[0]), "r"(a[1]), "r"(a[2]), "r"(a[3]), "r"(b[0]), "r"(b[1]));
}
__device__ __forceinline__ uint32_t packbf2(float x, float y) {
    __nv_bfloat162 v = __floats2bfloat162_rn(x, y);
    return *(uint32_t*)&v;
}

// ---------------- weight convert (transpose + bf16) ----------------
__global__ void conv_wt_kernel(const float* __restrict__ W0, const float* __restrict__ W1,
                               const float* __restrict__ W2, const float* __restrict__ W3) {
    __shared__ float tile[32][33];
    int which = blockIdx.z;
    const float* W = which == 0 ? W0 : (which == 1 ? W1 : (which == 2 ? W2 : W3));
    int k0 = blockIdx.x * 32, c0 = blockIdx.y * 32;
    int tx = threadIdx.x, ty = threadIdx.y;  // 32 x 8
    #pragma unroll
    for (int j = 0; j < 32; j += 8)
        tile[ty + j][tx] = W[(size_t)(k0 + ty + j) * HIDDEN + c0 + tx];
    __syncthreads();
    __nv_bfloat16* wt = g_wt[which];
    #pragma unroll
    for (int j = 0; j < 32; j += 8)
        wt[(size_t)(c0 + ty + j) * HIDDEN + k0 + tx] = __float2bfloat16(tile[tx][ty + j]);
}

// ---- hs bf16 conversion + 16-row column partial sums (512 CTAs) ----------
__global__ __launch_bounds__(192) void conv_sum_kernel(const float* __restrict__ hs) {
    int b = blockIdx.x, chunk = blockIdx.y, t = threadIdx.x;
    const float4* src = (const float4*)(hs + ((size_t)(b * SEQ + chunk * 16)) * HIDDEN);
    __nv_bfloat162* dst = (__nv_bfloat162*)(g_hs16 + ((size_t)(b * SEQ + chunk * 16)) * HIDDEN);
    float4 acc = make_float4(0.f, 0.f, 0.f, 0.f);
    #pragma unroll
    for (int r = 0; r < 16; r++) {
        float4 v = src[r * 192 + t];
        acc.x += v.x; acc.y += v.y; acc.z += v.z; acc.w += v.w;
        dst[2 * (r * 192 + t) + 0] = __floats2bfloat162_rn(v.x, v.y);
        dst[2 * (r * 192 + t) + 1] = __floats2bfloat162_rn(v.z, v.w);
    }
    *(float4*)&g_rsum[b][chunk][4 * t] = acc;
}

// ---- router: chunk-reduce + warp-per-head logits + topk, one launch ------
__global__ void router_kernel(const float* __restrict__ Wr, const float* __restrict__ br) {
    int b = blockIdx.x, t = threadIdx.x;
    __shared__ float ssum[HIDDEN];
    __shared__ float slog[NH];
    for (int d = t; d < HIDDEN; d += 256) {
        float a0 = 0.f, a1 = 0.f, a2 = 0.f, a3 = 0.f;
        #pragma unroll 4
        for (int c = 0; c < 64; c += 4) {
            a0 += g_rsum[b][c + 0][d];
            a1 += g_rsum[b][c + 1][d];
            a2 += g_rsum[b][c + 2][d];
            a3 += g_rsum[b][c + 3][d];
        }
        ssum[d] = (a0 + a1) + (a2 + a3);
    }
    __syncthreads();
    int wid = t >> 5, lane = t & 31;
    for (int h = wid; h < NH; h += 8) {
        float acc = 0.f;
        #pragma unroll
        for (int i = 0; i < HIDDEN / 32; i++) {
            int d = i * 32 + lane;
            acc += ssum[d] * Wr[d * NH + h];
        }
        #pragma unroll
        for (int o = 16; o > 0; o >>= 1)
            acc += __shfl_xor_sync(0xFFFFFFFF, acc, o);
        if (lane == 0) slog[h] = acc / (float)SEQ + br[h];
    }
    __syncthreads();
    if (t == 0) {
        bool sel[NH];
        #pragma unroll
        for (int h = 0; h < NH; h++) sel[h] = false;
        for (int k = 0; k < KSEL; k++) {
            int best = -1; float bv = 0.f;
            for (int h = 0; h < NH; h++)
                if (!sel[h] && (best < 0 || slog[h] > bv)) { bv = slog[h]; best = h; }
            sel[best] = true;
        }
        for (int h = 0; h < NH; h++) g_mask[b][h] = sel[h] ? 1.f : 0.f;
    }
}

// ---- QKV: HMMA bf16 GEMM, 256m x 64n CTA tile, warp = 32m x 64n ----------
// smem: A 2 x 32KB @0 ; B 2 x 8KB @65536 => 80KB
#define QKV_SMEM 81920

__global__ __launch_bounds__(256) void qkv_hmma_kernel(const float* __restrict__ bq,
                                                       const float* __restrict__ bk,
                                                       const float* __restrict__ bv) {
    int t = threadIdx.x, wid = t >> 5, lane = t & 31;
    int s0 = blockIdx.x * 256;
    int h = blockIdx.y % NH, b = blockIdx.y / NH;
    int sec = blockIdx.z;
    if (g_mask[b][h] == 0.f) return;

    extern __shared__ char dsm[];
    uint32_t sbA = smem_u32(dsm);           // 2 x 32768
    uint32_t sbB = sbA + 65536;             // 2 x 8192

    const __nv_bfloat16* Asrc = g_hs16 + ((size_t)(b * SEQ + s0)) * HIDDEN;
    const __nv_bfloat16* Bsrc = g_wt[sec] + ((size_t)h * 64) * HIDDEN;

    int m0 = wid * 32;
    float acc[2][8][4];
    #pragma unroll
    for (int i = 0; i < 2; i++)
        #pragma unroll
        for (int j = 0; j < 8; j++)
            #pragma unroll
            for (int x = 0; x < 4; x++) acc[i][j][x] = 0.f;

    auto load_chunk = [&](int buf, int k0) {
        uint32_t ab = sbA + buf * 32768;
        #pragma unroll
        for (int i = 0; i < 8; i++) {
            int u = i * 256 + t, row = u >> 3, ch = u & 7;
            cp16(ab + SWZ(row * 128 + ch * 16), Asrc + (size_t)row * HIDDEN + k0 + ch * 8);
        }
        uint32_t bb = sbB + buf * 8192;
        #pragma unroll
        for (int i = 0; i < 2; i++) {
            int u = i * 256 + t, row = u >> 3, ch = u & 7;
            cp16(bb + SWZ(row * 128 + ch * 16), Bsrc + (size_t)row * HIDDEN + k0 + ch * 8);
        }
    };

    load_chunk(0, 0);
    CP_COMMIT();
    int cur = 0;
    const int NC = HIDDEN / 64;
    int rowA = m0 + ((lane >> 3) & 1) * 8 + (lane & 7);
    int koA  = (lane >> 4) * 16;
    int rowB = (lane >> 4) * 8 + (lane & 7);    // + hf*16
    int koB  = ((lane >> 3) & 1) * 16;
    for (int c = 0; c < NC; c++) {
        CP_WAIT0();
        __syncthreads();
        if (c + 1 < NC) { load_chunk(cur ^ 1, (c + 1) * 64); CP_COMMIT(); }
        uint32_t aBase = sbA + cur * 32768;
        uint32_t bBase = sbB + cur * 8192;
        #pragma unroll
        for (int kk = 0; kk < 4; kk++) {
            int kb = kk * 32;
            uint32_t a[2][4], bf[4][4];
            #pragma unroll
            for (int mt = 0; mt < 2; mt++)
                ldm_x4(a[mt], aBase + SWZ((rowA + mt * 16) * 128 + kb + koA));
            #pragma unroll
            for (int hf = 0; hf < 4; hf++)
                ldm_x4(bf[hf], bBase + SWZ((rowB + hf * 16) * 128 + kb + koB));
            #pragma unroll
            for (int mt = 0; mt < 2; mt++)
                #pragma unroll
                for (int nt = 0; nt < 8; nt++)
                    mma16816(acc[mt][nt], a[mt], &bf[nt >> 1][(nt & 1) * 2]);
        }
        cur ^= 1;
    }

    const float* bias = sec == 0 ? bq : (sec == 1 ? bk : bv);
    __nv_bfloat16* base = sec == 0 ? g_q16 : (sec == 1 ? g_k16 : g_v16);
    __nv_bfloat16* dst = base + (((size_t)b * NH + h) * SEQ + s0) * HD;
    #pragma unroll
    for (int mt = 0; mt < 2; mt++)
        #pragma unroll
        for (int nt = 0; nt < 8; nt++) {
            int r = m0 + mt * 16 + (lane >> 2);
            int cc = nt * 8 + (lane & 3) * 2;
            float b0 = bias[h * 64 + cc], b1 = bias[h * 64 + cc + 1];
            *(__nv_bfloat162*)(dst + (size_t)r * HD + cc) =
                __floats2bfloat162_rn(acc[mt][nt][0] + b0, acc[mt][nt][1] + b1);
            *(__nv_bfloat162*)(dst + (size_t)(r + 8) * HD + cc) =
                __floats2bfloat162_rn(acc[mt][nt][2] + b0, acc[mt][nt][3] + b1);
        }
}

// ---------------- attention: HMMA flash (no max-shift; scores bounded) -----
#define ATT_SMEM 49152

__global__ __launch_bounds__(256, 2) void attn_hmma_kernel() {
    int b = blockIdx.y / NH, h = blockIdx.y % NH;
    if (g_mask[b][h] == 0.f) return;
    int t = threadIdx.x, wid = t >> 5, lane = t & 31;
    int s0 = blockIdx.x * 128;

    extern __shared__ char dsm[];
    uint32_t sQ = smem_u32(dsm);
    uint32_t sK = sQ + 16384;
    uint32_t sV = sQ + 32768;

    const __nv_bfloat16* qsrc = g_q16 + (((size_t)b * NH + h) * SEQ + s0) * HD;
    const __nv_bfloat16* ksrc = g_k16 + (((size_t)b * NH + h) * SEQ) * HD;
    const __nv_bfloat16* vsrc = g_v16 + (((size_t)b * NH + h) * SEQ) * HD;

    #pragma unroll
    for (int i = 0; i < 4; i++) {
        int u = i * 256 + t, row = u >> 3, ch = u & 7;
        cp16(sQ + SWZ(row * 128 + ch * 16), qsrc + (size_t)row * HD + ch * 8);
    }
    auto load_kv = [&](int buf, int kt) {
        #pragma unroll
        for (int i = 0; i < 2; i++) {
            int u = i * 256 + t, row = u >> 3, ch = u & 7;
            cp16(sK + buf * 8192 + SWZ(row * 128 + ch * 16),
                 ksrc + (size_t)(kt * 64 + row) * HD + ch * 8);
            cp16(sV + buf * 8192 + SWZ(row * 128 + ch * 16),
                 vsrc + (size_t)(kt * 64 + row) * HD + ch * 8);
        }
    };
    load_kv(0, 0);
    CP_COMMIT();

    int m0 = wid * 16;
    float o[8][4];
    #pragma unroll
    for (int i = 0; i < 8; i++)
        #pragma unroll
        for (int j = 0; j < 4; j++) o[i][j] = 0.f;
    float l0 = 0.f, l1 = 0.f;

    int rowA = m0 + ((lane >> 3) & 1) * 8 + (lane & 7);
    int koA  = (lane >> 4) * 16;
    int rowBb = (lane >> 4) * 8 + (lane & 7);
    int koB  = ((lane >> 3) & 1) * 16;
    int rowV = ((lane >> 3) & 1) * 8 + (lane & 7);
    int koV  = ((lane >> 4) & 1) * 16;

    int cur = 0;
    for (int kt = 0; kt < SEQ / 64; kt++) {
        CP_WAIT0();
        __syncthreads();
        if (kt + 1 < SEQ / 64) { load_kv(cur ^ 1, kt + 1); CP_COMMIT(); }

        uint32_t kBase = sK + cur * 8192;
        uint32_t vBase = sV + cur * 8192;

        float s[8][4];
        #pragma unroll
        for (int i = 0; i < 8; i++)
            #pragma unroll
            for (int j = 0; j < 4; j++) s[i][j] = 0.f;
        #pragma unroll
        for (int ds = 0; ds < 4; ds++) {
            uint32_t qa[4];
            ldm_x4(qa, sQ + SWZ(rowA * 128 + ds * 32 + koA));
            #pragma unroll
            for (int nf = 0; nf < 4; nf++) {
                uint32_t kb4[4];
                ldm_x4(kb4, kBase + SWZ((nf * 16 + rowBb) * 128 + ds * 32 + koB));
                mma16816(s[2 * nf + 0], qa, &kb4[0]);
                mma16816(s[2 * nf + 1], qa, &kb4[2]);
            }
        }
        uint32_t pa[4][4];
        #pragma unroll
        for (int nf = 0; nf < 8; nf++) {
            s[nf][0] = __expf(s[nf][0] * 0.125f);
            s[nf][1] = __expf(s[nf][1] * 0.125f);
            s[nf][2] = __expf(s[nf][2] * 0.125f);
            s[nf][3] = __expf(s[nf][3] * 0.125f);
            l0 += s[nf][0] + s[nf][1];
            l1 += s[nf][2] + s[nf][3];
        }
        #pragma unroll
        for (int ks = 0; ks < 4; ks++) {
            pa[ks][0] = packbf2(s[2 * ks][0],     s[2 * ks][1]);
            pa[ks][1] = packbf2(s[2 * ks][2],     s[2 * ks][3]);
            pa[ks][2] = packbf2(s[2 * ks + 1][0], s[2 * ks + 1][1]);
            pa[ks][3] = packbf2(s[2 * ks + 1][2], s[2 * ks + 1][3]);
        }
        #pragma unroll
        for (int ks = 0; ks < 4; ks++) {
            #pragma unroll
            for (int dh = 0; dh < 4; dh++) {
                uint32_t vb[4];
                ldm_x4t(vb, vBase + SWZ((ks * 16 + rowV) * 128 + dh * 32 + koV));
                mma16816(o[2 * dh + 0], pa[ks], &vb[0]);
                mma16816(o[2 * dh + 1], pa[ks], &vb[2]);
            }
        }
        cur ^= 1;
    }

    l0 += __shfl_xor_sync(0xFFFFFFFF, l0, 1);
    l0 += __shfl_xor_sync(0xFFFFFFFF, l0, 2);
    l1 += __shfl_xor_sync(0xFFFFFFFF, l1, 1);
    l1 += __shfl_xor_sync(0xFFFFFFFF, l1, 2);
    float inv0 = 1.f / l0, inv1 = 1.f / l1;

    int r0 = s0 + m0 + (lane >> 2);
    __nv_bfloat16* c0 = g_ctx16 + ((size_t)(b * SEQ + r0)) * HIDDEN + h * 64;
    __nv_bfloat16* c1 = c0 + (size_t)8 * HIDDEN;
    #pragma unroll
    for (int dn = 0; dn < 8; dn++) {
        int d = dn * 8 + (lane & 3) * 2;
        *(__nv_bfloat162*)(c0 + d) = __floats2bfloat162_rn(o[dn][0] * inv0, o[dn][1] * inv0);
        *(__nv_bfloat162*)(c1 + d) = __floats2bfloat162_rn(o[dn][2] * inv1, o[dn][3] * inv1);
    }
}

// ---------------- Wo: HMMA bf16, active-head K only, bias+residual fused ---
#define WO_SMEM 65536

__global__ __launch_bounds__(256) void wo_hmma_kernel(const float* __restrict__ hs,
                                                      const float* __restrict__ bo,
                                                      float* __restrict__ out) {
    int t = threadIdx.x, wid = t >> 5, lane = t & 31;
    int s0 = blockIdx.x * 128;
    int col0 = blockIdx.y * 128;
    int b = blockIdx.z;

    int act[KSEL]; int na = 0;
    #pragma unroll
    for (int h = 0; h < NH; h++)
        if (g_mask[b][h] != 0.f) { if (na < KSEL) act[na] = h; na++; }

    extern __shared__ char dsm[];
    uint32_t sbA = smem_u32(dsm);
    uint32_t sbB = sbA + 32768;

    int m0 = (wid & 3) * 32, n0 = (wid >> 2) * 64;
    float acc[2][8][4];
    #pragma unroll
    for (int i = 0; i < 2; i++)
        #pragma unroll
        for (int j = 0; j < 8; j++)
            #pragma unroll
            for (int x = 0; x < 4; x++) acc[i][j][x] = 0.f;

    auto load_chunk = [&](int buf, int h) {
        const __nv_bfloat16* Asrc = g_ctx16 + ((size_t)(b * SEQ + s0)) * HIDDEN + h * 64;
        uint32_t ab = sbA + buf * 16384;
        #pragma unroll
        for (int i = 0; i < 4; i++) {
            int u = i * 256 + t, row = u >> 3, ch = u & 7;
            cp16(ab + SWZ(row * 128 + ch * 16), Asrc + (size_t)row * HIDDEN + ch * 8);
        }
        const __nv_bfloat16* Bsrc = g_wt[3] + ((size_t)col0) * HIDDEN + h * 64;
        uint32_t bb = sbB + buf * 16384;
        #pragma unroll
        for (int i = 0; i < 4; i++) {
            int u = i * 256 + t, row = u >> 3, ch = u & 7;
            cp16(bb + SWZ(row * 128 + ch * 16), Bsrc + (size_t)row * HIDDEN + ch * 8);
        }
    };

    load_chunk(0, act[0]);
    CP_COMMIT();
    int cur = 0;
    for (int c = 0; c < KSEL; c++) {
        CP_WAIT0();
        __syncthreads();
        if (c + 1 < KSEL) { load_chunk(cur ^ 1, act[c + 1]); CP_COMMIT(); }
        uint32_t aBase = sbA + cur * 16384;
        uint32_t bBase = sbB + cur * 16384;
        #pragma unroll
        for (int kk = 0; kk < 4; kk++) {
            int kb = kk * 32;
            uint32_t a[2][4], bf[4][4];
            #pragma unroll
            for (int mt = 0; mt < 2; mt++) {
                int row = m0 + mt * 16 + ((lane >> 3) & 1) * 8 + (lane & 7);
                int ko = kb + (lane >> 4) * 16;
                ldm_x4(a[mt], aBase + SWZ(row * 128 + ko));
            }
            #pragma unroll
            for (int hf = 0; hf < 4; hf++) {
                int row = n0 + hf * 16 + (lane >> 4) * 8 + (lane & 7);
                int ko = kb + ((lane >> 3) & 1) * 16;
                ldm_x4(bf[hf], bBase + SWZ(row * 128 + ko));
            }
            #pragma unroll
            for (int mt = 0; mt < 2; mt++)
                #pragma unroll
                for (int nt = 0; nt < 8; nt++)
                    mma16816(acc[mt][nt], a[mt], &bf[nt >> 1][(nt & 1) * 2]);
        }
        cur ^= 1;
    }

    #pragma unroll
    for (int mt = 0; mt < 2; mt++)
        #pragma unroll
        for (int nt = 0; nt < 8; nt++) {
            int r = s0 + m0 + mt * 16 + (lane >> 2);
            int cc = col0 + n0 + nt * 8 + (lane & 3) * 2;
            float b0 = bo[cc], b1 = bo[cc + 1];
            float2 r0 = *(const float2*)(hs + ((size_t)(b * SEQ + r)) * HIDDEN + cc);
            float2 r1 = *(const float2*)(hs + ((size_t)(b * SEQ + r + 8)) * HIDDEN + cc);
            float2 v0 = make_float2(acc[mt][nt][0] + b0 + r0.x, acc[mt][nt][1] + b1 + r0.y);
            float2 v1 = make_float2(acc[mt][nt][2] + b0 + r1.x, acc[mt][nt][3] + b1 + r1.y);
            *(float2*)(out + ((size_t)(b * SEQ + r)) * HIDDEN + cc) = v0;
            *(float2*)(out + ((size_t)(b * SEQ + r + 8)) * HIDDEN + cc) = v1;
        }
}

// ---------------- LayerNorm in-place ----------------
__global__ void ln_kernel(float* __restrict__ x, const float* __restrict__ g,
                          const float* __restrict__ bb) {
    int row = blockIdx.x;
    int t = threadIdx.x;
    float* p = x + (size_t)row * HIDDEN;
    float v0 = p[t], v1 = p[t + 256], v2 = p[t + 512];
    __shared__ float red[256];
    red[t] = v0 + v1 + v2;
    __syncthreads();
    for (int o = 128; o > 0; o >>= 1) { if (t < o) red[t] += red[t + o]; __syncthreads(); }
    float mu = red[0] * (1.f / HIDDEN);
    __syncthreads();
    float d0 = v0 - mu, d1 = v1 - mu, d2 = v2 - mu;
    red[t] = d0 * d0 + d1 * d1 + d2 * d2;
    __syncthreads();
    for (int o = 128; o > 0; o >>= 1) { if (t < o) red[t] += red[t + o]; __syncthreads(); }
    float rs = rsqrtf(red[0] * (1.f / HIDDEN) + 1e-12f);
    p[t]       = d0 * rs * g[t]       + bb[t];
    p[t + 256] = d1 * rs * g[t + 256] + bb[t + 256];
    p[t + 512] = d2 * rs * g[t + 512] + bb[t + 512];
}

// ---------------------------------------------------------------------------
extern "C" void kernel_launch(void* const* d_in, const int* in_sizes, int n_in,
                              void* d_out, int out_size) {
    (void)in_sizes; (void)n_in; (void)out_size;
    const float* hs = (const float*)d_in[0];
    const float* Wq = (const float*)d_in[1];
    const float* bq = (const float*)d_in[2];
    const float* Wk = (const float*)d_in[3];
    const float* bk = (const float*)d_in[4];
    const float* Wv = (const float*)d_in[5];
    const float* bv = (const float*)d_in[6];
    const float* Wr = (const float*)d_in[7];
    const float* br = (const float*)d_in[8];
    const float* Wo = (const float*)d_in[9];
    const float* bo = (const float*)d_in[10];
    const float* lg = (const float*)d_in[11];
    const float* lb = (const float*)d_in[12];
    float* out = (float*)d_out;

    cudaFuncSetAttribute(qkv_hmma_kernel, cudaFuncAttributeMaxDynamicSharedMemorySize, QKV_SMEM);
    cudaFuncSetAttribute(attn_hmma_kernel, cudaFuncAttributeMaxDynamicSharedMemorySize, ATT_SMEM);
    cudaFuncSetAttribute(wo_hmma_kernel,  cudaFuncAttributeMaxDynamicSharedMemorySize, WO_SMEM);

    conv_wt_kernel<<<dim3(24, 24, 4), dim3(32, 8)>>>(Wq, Wk, Wv, Wo);
    conv_sum_kernel<<<dim3(BATCH, 64), 192>>>(hs);
    router_kernel<<<BATCH, 256>>>(Wr, br);
    qkv_hmma_kernel<<<dim3(SEQ / 256, BATCH * NH, 3), 256, QKV_SMEM>>>(bq, bk, bv);
    attn_hmma_kernel<<<dim3(SEQ / 128, BATCH * NH), 256, ATT_SMEM>>>();
    wo_hmma_kernel<<<dim3(SEQ / 128, HIDDEN / 128, BATCH), 256, WO_SMEM>>>(hs, bo, out);
    ln_kernel<<<BATCH * SEQ, 256>>>(out, lg, lb);
}

// round 14
// speedup vs baseline: 1.3088x; 1.1001x over previous
#include <cuda_runtime.h>
#include <cuda_bf16.h>
#include <cstdint>

#define BATCH  8
#define SEQ    1024
#define NH     12
#define HD     64
#define HIDDEN 768
#define KSEL   6

// ---------------- device scratch (no allocations allowed) ----------------
__device__ float g_mask[BATCH][NH];
__device__ float g_rsum[BATCH][64][HIDDEN];
__device__ __align__(16) __nv_bfloat16 g_q16[(size_t)BATCH * NH * SEQ * HD];
__device__ __align__(16) __nv_bfloat16 g_k16[(size_t)BATCH * NH * SEQ * HD];
__device__ __align__(16) __nv_bfloat16 g_v16[(size_t)BATCH * NH * SEQ * HD];
__device__ __align__(16) __nv_bfloat16 g_hs16[(size_t)BATCH * SEQ * HIDDEN];
__device__ __align__(16) __nv_bfloat16 g_ctx16[(size_t)BATCH * SEQ * HIDDEN];
__device__ __align__(16) __nv_bfloat16 g_wt[4][(size_t)HIDDEN * HIDDEN]; // transposed: wt[c][k]=W[k][c]

// ---------------- helpers ----------------
__device__ __forceinline__ uint32_t smem_u32(const void* p) {
    uint32_t a;
    asm("{ .reg .u64 t; cvta.to.shared.u64 t, %1; cvt.u32.u64 %0, t; }" : "=r"(a) : "l"(p));
    return a;
}
#define SWZ(x) ((x) ^ (((x) >> 3) & 0x70))

__device__ __forceinline__ void cp16(uint32_t saddr, const void* g) {
    asm volatile("cp.async.cg.shared.global [%0], [%1], 16;" :: "r"(saddr), "l"(g));
}
#define CP_COMMIT() asm volatile("cp.async.commit_group;")
#define CP_WAIT0()  asm volatile("cp.async.wait_group 0;")

__device__ __forceinline__ void ldm_x4(uint32_t* r, uint32_t addr) {
    asm volatile("ldmatrix.sync.aligned.m8n8.x4.shared.b16 {%0,%1,%2,%3}, [%4];"
                 : "=r"(r[0]), "=r"(r[1]), "=r"(r[2]), "=r"(r[3]) : "r"(addr));
}
__device__ __forceinline__ void ldm_x4t(uint32_t* r, uint32_t addr) {
    asm volatile("ldmatrix.sync.aligned.m8n8.x4.trans.shared.b16 {%0,%1,%2,%3}, [%4];"
                 : "=r"(r[0]), "=r"(r[1]), "=r"(r[2]), "=r"(r[3]) : "r"(addr));
}
__device__ __forceinline__ void mma16816(float* c, const uint32_t* a, const uint32_t* b) {
    asm volatile(
        "mma.sync.aligned.m16n8k16.row.col.f32.bf16.bf16.f32 "
        "{%0,%1,%2,%3}, {%4,%5,%6,%7}, {%8,%9}, {%0,%1,%2,%3};"
        : "+f"(c[0]), "+f"(c[1]), "+f"(c[2]), "+f"(c[3])
        : "r"(a[0]), "r"(a[1]), "r"(a[2]), "r"(a[3]), "r"(b[0]), "r"(b[1]));
}
__device__ __forceinline__ uint32_t packbf2(float x, float y) {
    __nv_bfloat162 v = __floats2bfloat162_rn(x, y);
    return *(uint32_t*)&v;
}

// ---------------- weight convert (transpose + bf16) ----------------
__global__ void conv_wt_kernel(const float* __restrict__ W0, const float* __restrict__ W1,
                               const float* __restrict__ W2, const float* __restrict__ W3) {
    __shared__ float tile[32][33];
    int which = blockIdx.z;
    const float* W = which == 0 ? W0 : (which == 1 ? W1 : (which == 2 ? W2 : W3));
    int k0 = blockIdx.x * 32, c0 = blockIdx.y * 32;
    int tx = threadIdx.x, ty = threadIdx.y;  // 32 x 8
    #pragma unroll
    for (int j = 0; j < 32; j += 8)
        tile[ty + j][tx] = W[(size_t)(k0 + ty + j) * HIDDEN + c0 + tx];
    __syncthreads();
    __nv_bfloat16* wt = g_wt[which];
    #pragma unroll
    for (int j = 0; j < 32; j += 8)
        wt[(size_t)(c0 + ty + j) * HIDDEN + k0 + tx] = __float2bfloat16(tile[tx][ty + j]);
}

// ---- hs bf16 conversion + 16-row column partial sums (512 CTAs) ----------
__global__ __launch_bounds__(192) void conv_sum_kernel(const float* __restrict__ hs) {
    int b = blockIdx.x, chunk = blockIdx.y, t = threadIdx.x;
    const float4* src = (const float4*)(hs + ((size_t)(b * SEQ + chunk * 16)) * HIDDEN);
    __nv_bfloat162* dst = (__nv_bfloat162*)(g_hs16 + ((size_t)(b * SEQ + chunk * 16)) * HIDDEN);
    float4 acc = make_float4(0.f, 0.f, 0.f, 0.f);
    #pragma unroll
    for (int r = 0; r < 16; r++) {
        float4 v = src[r * 192 + t];
        acc.x += v.x; acc.y += v.y; acc.z += v.z; acc.w += v.w;
        dst[2 * (r * 192 + t) + 0] = __floats2bfloat162_rn(v.x, v.y);
        dst[2 * (r * 192 + t) + 1] = __floats2bfloat162_rn(v.z, v.w);
    }
    *(float4*)&g_rsum[b][chunk][4 * t] = acc;
}

// ---- router: chunk-reduce + warp-per-head logits + topk, one launch ------
__global__ void router_kernel(const float* __restrict__ Wr, const float* __restrict__ br) {
    int b = blockIdx.x, t = threadIdx.x;
    __shared__ float ssum[HIDDEN];
    __shared__ float slog[NH];
    for (int d = t; d < HIDDEN; d += 256) {
        float a0 = 0.f, a1 = 0.f, a2 = 0.f, a3 = 0.f;
        #pragma unroll 4
        for (int c = 0; c < 64; c += 4) {
            a0 += g_rsum[b][c + 0][d];
            a1 += g_rsum[b][c + 1][d];
            a2 += g_rsum[b][c + 2][d];
            a3 += g_rsum[b][c + 3][d];
        }
        ssum[d] = (a0 + a1) + (a2 + a3);
    }
    __syncthreads();
    int wid = t >> 5, lane = t & 31;
    for (int h = wid; h < NH; h += 8) {
        float acc = 0.f;
        #pragma unroll
        for (int i = 0; i < HIDDEN / 32; i++) {
            int d = i * 32 + lane;
            acc += ssum[d] * Wr[d * NH + h];
        }
        #pragma unroll
        for (int o = 16; o > 0; o >>= 1)
            acc += __shfl_xor_sync(0xFFFFFFFF, acc, o);
        if (lane == 0) slog[h] = acc / (float)SEQ + br[h];
    }
    __syncthreads();
    if (t == 0) {
        bool sel[NH];
        #pragma unroll
        for (int h = 0; h < NH; h++) sel[h] = false;
        for (int k = 0; k < KSEL; k++) {
            int best = -1; float bv = 0.f;
            for (int h = 0; h < NH; h++)
                if (!sel[h] && (best < 0 || slog[h] > bv)) { bv = slog[h]; best = h; }
            sel[best] = true;
        }
        for (int h = 0; h < NH; h++) g_mask[b][h] = sel[h] ? 1.f : 0.f;
    }
}

// ---- QKV: HMMA bf16 GEMM, 256m x 64n CTA tile, warp = 32m x 64n ----------
#define QKV_SMEM 81920

__global__ __launch_bounds__(256) void qkv_hmma_kernel(const float* __restrict__ bq,
                                                       const float* __restrict__ bk,
                                                       const float* __restrict__ bv) {
    int t = threadIdx.x, wid = t >> 5, lane = t & 31;
    int s0 = blockIdx.x * 256;
    int h = blockIdx.y % NH, b = blockIdx.y / NH;
    int sec = blockIdx.z;
    if (g_mask[b][h] == 0.f) return;

    extern __shared__ char dsm[];
    uint32_t sbA = smem_u32(dsm);           // 2 x 32768
    uint32_t sbB = sbA + 65536;             // 2 x 8192

    const __nv_bfloat16* Asrc = g_hs16 + ((size_t)(b * SEQ + s0)) * HIDDEN;
    const __nv_bfloat16* Bsrc = g_wt[sec] + ((size_t)h * 64) * HIDDEN;

    int m0 = wid * 32;
    float acc[2][8][4];
    #pragma unroll
    for (int i = 0; i < 2; i++)
        #pragma unroll
        for (int j = 0; j < 8; j++)
            #pragma unroll
            for (int x = 0; x < 4; x++) acc[i][j][x] = 0.f;

    auto load_chunk = [&](int buf, int k0) {
        uint32_t ab = sbA + buf * 32768;
        #pragma unroll
        for (int i = 0; i < 8; i++) {
            int u = i * 256 + t, row = u >> 3, ch = u & 7;
            cp16(ab + SWZ(row * 128 + ch * 16), Asrc + (size_t)row * HIDDEN + k0 + ch * 8);
        }
        uint32_t bb = sbB + buf * 8192;
        #pragma unroll
        for (int i = 0; i < 2; i++) {
            int u = i * 256 + t, row = u >> 3, ch = u & 7;
            cp16(bb + SWZ(row * 128 + ch * 16), Bsrc + (size_t)row * HIDDEN + k0 + ch * 8);
        }
    };

    load_chunk(0, 0);
    CP_COMMIT();
    int cur = 0;
    const int NC = HIDDEN / 64;
    int rowA = m0 + ((lane >> 3) & 1) * 8 + (lane & 7);
    int koA  = (lane >> 4) * 16;
    int rowB = (lane >> 4) * 8 + (lane & 7);
    int koB  = ((lane >> 3) & 1) * 16;
    for (int c = 0; c < NC; c++) {
        CP_WAIT0();
        __syncthreads();
        if (c + 1 < NC) { load_chunk(cur ^ 1, (c + 1) * 64); CP_COMMIT(); }
        uint32_t aBase = sbA + cur * 32768;
        uint32_t bBase = sbB + cur * 8192;
        #pragma unroll
        for (int kk = 0; kk < 4; kk++) {
            int kb = kk * 32;
            uint32_t a[2][4], bf[4][4];
            #pragma unroll
            for (int mt = 0; mt < 2; mt++)
                ldm_x4(a[mt], aBase + SWZ((rowA + mt * 16) * 128 + kb + koA));
            #pragma unroll
            for (int hf = 0; hf < 4; hf++)
                ldm_x4(bf[hf], bBase + SWZ((rowB + hf * 16) * 128 + kb + koB));
            #pragma unroll
            for (int mt = 0; mt < 2; mt++)
                #pragma unroll
                for (int nt = 0; nt < 8; nt++)
                    mma16816(acc[mt][nt], a[mt], &bf[nt >> 1][(nt & 1) * 2]);
        }
        cur ^= 1;
    }

    const float* bias = sec == 0 ? bq : (sec == 1 ? bk : bv);
    __nv_bfloat16* base = sec == 0 ? g_q16 : (sec == 1 ? g_k16 : g_v16);
    __nv_bfloat16* dst = base + (((size_t)b * NH + h) * SEQ + s0) * HD;
    #pragma unroll
    for (int mt = 0; mt < 2; mt++)
        #pragma unroll
        for (int nt = 0; nt < 8; nt++) {
            int r = m0 + mt * 16 + (lane >> 2);
            int cc = nt * 8 + (lane & 3) * 2;
            float b0 = bias[h * 64 + cc], b1 = bias[h * 64 + cc + 1];
            *(__nv_bfloat162*)(dst + (size_t)r * HD + cc) =
                __floats2bfloat162_rn(acc[mt][nt][0] + b0, acc[mt][nt][1] + b1);
            *(__nv_bfloat162*)(dst + (size_t)(r + 8) * HD + cc) =
                __floats2bfloat162_rn(acc[mt][nt][2] + b0, acc[mt][nt][3] + b1);
        }
}

// ---- attention: HMMA flash, 64 q-rows / 128 threads per CTA --------------
// smem: Q 8KB @0; K 2x8KB @8192; V 2x8KB @24576 => 40KB
#define ATT_SMEM 40960

__global__ __launch_bounds__(128, 4) void attn_hmma_kernel() {
    int b = blockIdx.y / NH, h = blockIdx.y % NH;
    if (g_mask[b][h] == 0.f) return;
    int t = threadIdx.x, wid = t >> 5, lane = t & 31;
    int s0 = blockIdx.x * 64;

    extern __shared__ char dsm[];
    uint32_t sQ = smem_u32(dsm);
    uint32_t sK = sQ + 8192;
    uint32_t sV = sQ + 24576;

    const __nv_bfloat16* qsrc = g_q16 + (((size_t)b * NH + h) * SEQ + s0) * HD;
    const __nv_bfloat16* ksrc = g_k16 + (((size_t)b * NH + h) * SEQ) * HD;
    const __nv_bfloat16* vsrc = g_v16 + (((size_t)b * NH + h) * SEQ) * HD;

    #pragma unroll
    for (int i = 0; i < 4; i++) {
        int u = i * 128 + t, row = u >> 3, ch = u & 7;
        cp16(sQ + SWZ(row * 128 + ch * 16), qsrc + (size_t)row * HD + ch * 8);
    }
    auto load_kv = [&](int buf, int kt) {
        #pragma unroll
        for (int i = 0; i < 4; i++) {
            int u = i * 128 + t, row = u >> 3, ch = u & 7;
            cp16(sK + buf * 8192 + SWZ(row * 128 + ch * 16),
                 ksrc + (size_t)(kt * 64 + row) * HD + ch * 8);
            cp16(sV + buf * 8192 + SWZ(row * 128 + ch * 16),
                 vsrc + (size_t)(kt * 64 + row) * HD + ch * 8);
        }
    };
    load_kv(0, 0);
    CP_COMMIT();

    int m0 = wid * 16;
    float o[8][4];
    #pragma unroll
    for (int i = 0; i < 8; i++)
        #pragma unroll
        for (int j = 0; j < 4; j++) o[i][j] = 0.f;
    float l0 = 0.f, l1 = 0.f;

    int rowA = m0 + ((lane >> 3) & 1) * 8 + (lane & 7);
    int koA  = (lane >> 4) * 16;
    int rowBb = (lane >> 4) * 8 + (lane & 7);
    int koB  = ((lane >> 3) & 1) * 16;
    int rowV = ((lane >> 3) & 1) * 8 + (lane & 7);
    int koV  = ((lane >> 4) & 1) * 16;

    int cur = 0;
    for (int kt = 0; kt < SEQ / 64; kt++) {
        CP_WAIT0();
        __syncthreads();
        if (kt + 1 < SEQ / 64) { load_kv(cur ^ 1, kt + 1); CP_COMMIT(); }

        uint32_t kBase = sK + cur * 8192;
        uint32_t vBase = sV + cur * 8192;

        float s[8][4];
        #pragma unroll
        for (int i = 0; i < 8; i++)
            #pragma unroll
            for (int j = 0; j < 4; j++) s[i][j] = 0.f;
        #pragma unroll
        for (int ds = 0; ds < 4; ds++) {
            uint32_t qa[4];
            ldm_x4(qa, sQ + SWZ(rowA * 128 + ds * 32 + koA));
            #pragma unroll
            for (int nf = 0; nf < 4; nf++) {
                uint32_t kb4[4];
                ldm_x4(kb4, kBase + SWZ((nf * 16 + rowBb) * 128 + ds * 32 + koB));
                mma16816(s[2 * nf + 0], qa, &kb4[0]);
                mma16816(s[2 * nf + 1], qa, &kb4[2]);
            }
        }
        uint32_t pa[4][4];
        #pragma unroll
        for (int nf = 0; nf < 8; nf++) {
            s[nf][0] = __expf(s[nf][0] * 0.125f);
            s[nf][1] = __expf(s[nf][1] * 0.125f);
            s[nf][2] = __expf(s[nf][2] * 0.125f);
            s[nf][3] = __expf(s[nf][3] * 0.125f);
            l0 += s[nf][0] + s[nf][1];
            l1 += s[nf][2] + s[nf][3];
        }
        #pragma unroll
        for (int ks = 0; ks < 4; ks++) {
            pa[ks][0] = packbf2(s[2 * ks][0],     s[2 * ks][1]);
            pa[ks][1] = packbf2(s[2 * ks][2],     s[2 * ks][3]);
            pa[ks][2] = packbf2(s[2 * ks + 1][0], s[2 * ks + 1][1]);
            pa[ks][3] = packbf2(s[2 * ks + 1][2], s[2 * ks + 1][3]);
        }
        #pragma unroll
        for (int ks = 0; ks < 4; ks++) {
            #pragma unroll
            for (int dh = 0; dh < 4; dh++) {
                uint32_t vb[4];
                ldm_x4t(vb, vBase + SWZ((ks * 16 + rowV) * 128 + dh * 32 + koV));
                mma16816(o[2 * dh + 0], pa[ks], &vb[0]);
                mma16816(o[2 * dh + 1], pa[ks], &vb[2]);
            }
        }
        cur ^= 1;
    }

    l0 += __shfl_xor_sync(0xFFFFFFFF, l0, 1);
    l0 += __shfl_xor_sync(0xFFFFFFFF, l0, 2);
    l1 += __shfl_xor_sync(0xFFFFFFFF, l1, 1);
    l1 += __shfl_xor_sync(0xFFFFFFFF, l1, 2);
    float inv0 = 1.f / l0, inv1 = 1.f / l1;

    int r0 = s0 + m0 + (lane >> 2);
    __nv_bfloat16* c0 = g_ctx16 + ((size_t)(b * SEQ + r0)) * HIDDEN + h * 64;
    __nv_bfloat16* c1 = c0 + (size_t)8 * HIDDEN;
    #pragma unroll
    for (int dn = 0; dn < 8; dn++) {
        int d = dn * 8 + (lane & 3) * 2;
        *(__nv_bfloat162*)(c0 + d) = __floats2bfloat162_rn(o[dn][0] * inv0, o[dn][1] * inv0);
        *(__nv_bfloat162*)(c1 + d) = __floats2bfloat162_rn(o[dn][2] * inv1, o[dn][3] * inv1);
    }
}

// ---------------- Wo: HMMA bf16, active-head K only, bias+residual fused ---
#define WO_SMEM 65536

__global__ __launch_bounds__(256) void wo_hmma_kernel(const float* __restrict__ hs,
                                                      const float* __restrict__ bo,
                                                      float* __restrict__ out) {
    int t = threadIdx.x, wid = t >> 5, lane = t & 31;
    int s0 = blockIdx.x * 128;
    int col0 = blockIdx.y * 128;
    int b = blockIdx.z;

    int act[KSEL]; int na = 0;
    #pragma unroll
    for (int h = 0; h < NH; h++)
        if (g_mask[b][h] != 0.f) { if (na < KSEL) act[na] = h; na++; }

    extern __shared__ char dsm[];
    uint32_t sbA = smem_u32(dsm);
    uint32_t sbB = sbA + 32768;

    int m0 = (wid & 3) * 32, n0 = (wid >> 2) * 64;
    float acc[2][8][4];
    #pragma unroll
    for (int i = 0; i < 2; i++)
        #pragma unroll
        for (int j = 0; j < 8; j++)
            #pragma unroll
            for (int x = 0; x < 4; x++) acc[i][j][x] = 0.f;

    auto load_chunk = [&](int buf, int h) {
        const __nv_bfloat16* Asrc = g_ctx16 + ((size_t)(b * SEQ + s0)) * HIDDEN + h * 64;
        uint32_t ab = sbA + buf * 16384;
        #pragma unroll
        for (int i = 0; i < 4; i++) {
            int u = i * 256 + t, row = u >> 3, ch = u & 7;
            cp16(ab + SWZ(row * 128 + ch * 16), Asrc + (size_t)row * HIDDEN + ch * 8);
        }
        const __nv_bfloat16* Bsrc = g_wt[3] + ((size_t)col0) * HIDDEN + h * 64;
        uint32_t bb = sbB + buf * 16384;
        #pragma unroll
        for (int i = 0; i < 4; i++) {
            int u = i * 256 + t, row = u >> 3, ch = u & 7;
            cp16(bb + SWZ(row * 128 + ch * 16), Bsrc + (size_t)row * HIDDEN + ch * 8);
        }
    };

    load_chunk(0, act[0]);
    CP_COMMIT();
    int cur = 0;
    for (int c = 0; c < KSEL; c++) {
        CP_WAIT0();
        __syncthreads();
        if (c + 1 < KSEL) { load_chunk(cur ^ 1, act[c + 1]); CP_COMMIT(); }
        uint32_t aBase = sbA + cur * 16384;
        uint32_t bBase = sbB + cur * 16384;
        #pragma unroll
        for (int kk = 0; kk < 4; kk++) {
            int kb = kk * 32;
            uint32_t a[2][4], bf[4][4];
            #pragma unroll
            for (int mt = 0; mt < 2; mt++) {
                int row = m0 + mt * 16 + ((lane >> 3) & 1) * 8 + (lane & 7);
                int ko = kb + (lane >> 4) * 16;
                ldm_x4(a[mt], aBase + SWZ(row * 128 + ko));
            }
            #pragma unroll
            for (int hf = 0; hf < 4; hf++) {
                int row = n0 + hf * 16 + (lane >> 4) * 8 + (lane & 7);
                int ko = kb + ((lane >> 3) & 1) * 16;
                ldm_x4(bf[hf], bBase + SWZ(row * 128 + ko));
            }
            #pragma unroll
            for (int mt = 0; mt < 2; mt++)
                #pragma unroll
                for (int nt = 0; nt < 8; nt++)
                    mma16816(acc[mt][nt], a[mt], &bf[nt >> 1][(nt & 1) * 2]);
        }
        cur ^= 1;
    }

    #pragma unroll
    for (int mt = 0; mt < 2; mt++)
        #pragma unroll
        for (int nt = 0; nt < 8; nt++) {
            int r = s0 + m0 + mt * 16 + (lane >> 2);
            int cc = col0 + n0 + nt * 8 + (lane & 3) * 2;
            float b0 = bo[cc], b1 = bo[cc + 1];
            float2 r0 = *(const float2*)(hs + ((size_t)(b * SEQ + r)) * HIDDEN + cc);
            float2 r1 = *(const float2*)(hs + ((size_t)(b * SEQ + r + 8)) * HIDDEN + cc);
            float2 v0 = make_float2(acc[mt][nt][0] + b0 + r0.x, acc[mt][nt][1] + b1 + r0.y);
            float2 v1 = make_float2(acc[mt][nt][2] + b0 + r1.x, acc[mt][nt][3] + b1 + r1.y);
            *(float2*)(out + ((size_t)(b * SEQ + r)) * HIDDEN + cc) = v0;
            *(float2*)(out + ((size_t)(b * SEQ + r + 8)) * HIDDEN + cc) = v1;
        }
}

// ---------------- LayerNorm in-place (192 threads, float4) ----------------
__global__ __launch_bounds__(192) void ln_kernel(float* __restrict__ x,
                                                 const float* __restrict__ g,
                                                 const float* __restrict__ bb) {
    int row = blockIdx.x;
    int t = threadIdx.x, wid = t >> 5, lane = t & 31;
    float4* p = (float4*)(x + (size_t)row * HIDDEN);
    float4 v = p[t];
    __shared__ float ws[6];

    float s = (v.x + v.y) + (v.z + v.w);
    #pragma unroll
    for (int o = 16; o > 0; o >>= 1) s += __shfl_xor_sync(0xFFFFFFFF, s, o);
    if (lane == 0) ws[wid] = s;
    __syncthreads();
    float mu = ((ws[0] + ws[1]) + (ws[2] + ws[3]) + (ws[4] + ws[5])) * (1.f / HIDDEN);
    __syncthreads();

    float dx = v.x - mu, dy = v.y - mu, dz = v.z - mu, dw = v.w - mu;
    float q = (dx * dx + dy * dy) + (dz * dz + dw * dw);
    #pragma unroll
    for (int o = 16; o > 0; o >>= 1) q += __shfl_xor_sync(0xFFFFFFFF, q, o);
    if (lane == 0) ws[wid] = q;
    __syncthreads();
    float var = ((ws[0] + ws[1]) + (ws[2] + ws[3]) + (ws[4] + ws[5])) * (1.f / HIDDEN);
    float rs = rsqrtf(var + 1e-12f);

    float4 gv = ((const float4*)g)[t];
    float4 bv = ((const float4*)bb)[t];
    float4 o4;
    o4.x = dx * rs * gv.x + bv.x;
    o4.y = dy * rs * gv.y + bv.y;
    o4.z = dz * rs * gv.z + bv.z;
    o4.w = dw * rs * gv.w + bv.w;
    p[t] = o4;
}

// ---------------------------------------------------------------------------
extern "C" void kernel_launch(void* const* d_in, const int* in_sizes, int n_in,
                              void* d_out, int out_size) {
    (void)in_sizes; (void)n_in; (void)out_size;
    const float* hs = (const float*)d_in[0];
    const float* Wq = (const float*)d_in[1];
    const float* bq = (const float*)d_in[2];
    const float* Wk = (const float*)d_in[3];
    const float* bk = (const float*)d_in[4];
    const float* Wv = (const float*)d_in[5];
    const float* bv = (const float*)d_in[6];
    const float* Wr = (const float*)d_in[7];
    const float* br = (const float*)d_in[8];
    const float* Wo = (const float*)d_in[9];
    const float* bo = (const float*)d_in[10];
    const float* lg = (const float*)d_in[11];
    const float* lb = (const float*)d_in[12];
    float* out = (float*)d_out;

    cudaFuncSetAttribute(qkv_hmma_kernel, cudaFuncAttributeMaxDynamicSharedMemorySize, QKV_SMEM);
    cudaFuncSetAttribute(attn_hmma_kernel, cudaFuncAttributeMaxDynamicSharedMemorySize, ATT_SMEM);
    cudaFuncSetAttribute(wo_hmma_kernel,  cudaFuncAttributeMaxDynamicSharedMemorySize, WO_SMEM);

    conv_wt_kernel<<<dim3(24, 24, 4), dim3(32, 8)>>>(Wq, Wk, Wv, Wo);
    conv_sum_kernel<<<dim3(BATCH, 64), 192>>>(hs);
    router_kernel<<<BATCH, 256>>>(Wr, br);
    qkv_hmma_kernel<<<dim3(SEQ / 256, BATCH * NH, 3), 256, QKV_SMEM>>>(bq, bk, bv);
    attn_hmma_kernel<<<dim3(SEQ / 64, BATCH * NH), 128, ATT_SMEM>>>();
    wo_hmma_kernel<<<dim3(SEQ / 128, HIDDEN / 128, BATCH), 256, WO_SMEM>>>(hs, bo, out);
    ln_kernel<<<BATCH * SEQ, 192>>>(out, lg, lb);
}